// round 5
// baseline (speedup 1.0000x reference)
#include <cuda_runtime.h>

// ---------------------------------------------------------------------------
// SelfAttention (SAGAN-style) fp32 pipeline:
//   f = x@Wf+bf, g = x@Wg+bg, hm = x@Wh+bh
//   s = g @ f^T (per batch), beta = softmax(s, axis=-1)
//   o = beta @ hm, out = x + o@Wv + bv
// Shapes: B=4, N=4096 (=64x64), C=256, Ck=32.
// All math fp32; inner products use packed fma.rn.f32x2 (FFMA2, sm_10x-only,
// 2x the 3-reg FFMA rate).
// ---------------------------------------------------------------------------

#define BATCH 4
#define NPIX  4096
#define CDIM  256
#define CKDIM 32
#define MROWS (BATCH * NPIX)   // 16384

// Scratch (static __device__ arrays: no allocation anywhere, per harness rules)
static __device__ float g_f [MROWS * CKDIM];                 //  2 MB
static __device__ float g_g [MROWS * CKDIM];                 //  2 MB
static __device__ float g_hm[MROWS * CDIM];                  // 16 MB
static __device__ float g_o [MROWS * CDIM];                  // 16 MB
static __device__ float g_s [(size_t)BATCH * NPIX * NPIX];   // 256 MB

// --- packed f32x2 helpers ---------------------------------------------------
#define FMA2(c, a, b) \
    asm("fma.rn.f32x2 %0, %1, %2, %0;" : "+l"(c) : "l"(a), "l"(b))
#define DUP2(d, s) \
    asm("mov.b64 %0, {%1, %1};" : "=l"(d) : "f"(s))
#define UNPK2(lo, hi, p) \
    asm("mov.b64 {%0, %1}, %2;" : "=f"(lo), "=f"(hi) : "l"(p))

// ---------------------------------------------------------------------------
// Generic tiled SGEMM: C[M,N] = A[M,K] @ op(B) (+ bias[N]) (+ res[M,N])
//   TRANS_B = false : B is [K,N] row-major
//   TRANS_B = true  : B is [N,K] row-major (C = A @ B^T)
// Requirements (guaranteed by call sites): M % 128 == 0, K % 8 == 0.
// N may be < 128 (guarded). Batched via blockIdx.z with element strides.
// Block tile 128x128xBK8, 256 threads, 8x8 per-thread microtile in 4 quadrants.
// ---------------------------------------------------------------------------
template<bool TRANS_B, bool HAS_BIAS, bool HAS_RES>
__global__ __launch_bounds__(256, 2)
void sgemm_kernel(const float* __restrict__ A, const float* __restrict__ B,
                  float* __restrict__ C,
                  const float* __restrict__ bias, const float* __restrict__ res,
                  int M, int N, int K,
                  long long sA, long long sB, long long sC)
{
    __shared__ float As[8][132];   // [k][m], pad->132 floats: conflict-free xpose stores
    __shared__ float Bs[8][132];   // [k][n]

    A += (size_t)blockIdx.z * sA;
    B += (size_t)blockIdx.z * sB;
    C += (size_t)blockIdx.z * sC;

    const int m0 = blockIdx.y * 128;
    const int n0 = blockIdx.x * 128;
    const int t  = threadIdx.x;

    // global->smem load mapping
    const int a_row  = t >> 1;          // 0..127 (tile row for A / NT-B)
    const int a_koff = (t & 1) * 4;     // 0 or 4
    const int b_kr   = t >> 5;          // 0..7   (NN-B k row)
    const int b_nc   = (t & 31) * 4;    // 0..124 (NN-B n col)

    // compute mapping: 16x16 threads, 4x4 outputs per quadrant
    const int tx = t & 15;
    const int ty = t >> 4;

    unsigned long long acc[2][2][4][2];   // [mquad][nquad][i][npair] = 64 floats
    #pragma unroll
    for (int im = 0; im < 2; im++)
      #pragma unroll
      for (int in = 0; in < 2; in++)
        #pragma unroll
        for (int i = 0; i < 4; i++)
          #pragma unroll
          for (int jp = 0; jp < 2; jp++)
            acc[im][in][i][jp] = 0ULL;

    for (int k0 = 0; k0 < K; k0 += 8) {
        float4 av = *(const float4*)(A + (size_t)(m0 + a_row) * K + (k0 + a_koff));
        float4 bv;
        if (TRANS_B) {
            int n = n0 + a_row;
            bv = (n < N) ? *(const float4*)(B + (size_t)n * K + (k0 + a_koff))
                         : make_float4(0.f, 0.f, 0.f, 0.f);
        } else {
            int n = n0 + b_nc;
            bv = (n < N) ? *(const float4*)(B + (size_t)(k0 + b_kr) * N + n)
                         : make_float4(0.f, 0.f, 0.f, 0.f);
        }
        __syncthreads();   // previous iter's smem reads done before overwrite
        As[a_koff + 0][a_row] = av.x;
        As[a_koff + 1][a_row] = av.y;
        As[a_koff + 2][a_row] = av.z;
        As[a_koff + 3][a_row] = av.w;
        if (TRANS_B) {
            Bs[a_koff + 0][a_row] = bv.x;
            Bs[a_koff + 1][a_row] = bv.y;
            Bs[a_koff + 2][a_row] = bv.z;
            Bs[a_koff + 3][a_row] = bv.w;
        } else {
            *(float4*)&Bs[b_kr][b_nc] = bv;
        }
        __syncthreads();

        #pragma unroll
        for (int kk = 0; kk < 8; kk++) {
            float4 a0 = *(const float4*)&As[kk][ty * 4];        // rows quad 0
            float4 a1 = *(const float4*)&As[kk][64 + ty * 4];   // rows quad 1
            // adjacent-n pairs straight out of smem as u64 (no packing movs)
            ulonglong2 b0 = *(const ulonglong2*)&Bs[kk][tx * 4];
            ulonglong2 b1 = *(const ulonglong2*)&Bs[kk][64 + tx * 4];
            float am[2][4] = {{a0.x, a0.y, a0.z, a0.w},
                              {a1.x, a1.y, a1.z, a1.w}};
            unsigned long long bp[2][2] = {{b0.x, b0.y}, {b1.x, b1.y}};
            #pragma unroll
            for (int im = 0; im < 2; im++)
              #pragma unroll
              for (int i = 0; i < 4; i++) {
                  unsigned long long aa;
                  DUP2(aa, am[im][i]);
                  #pragma unroll
                  for (int in = 0; in < 2; in++)
                    #pragma unroll
                    for (int jp = 0; jp < 2; jp++)
                        FMA2(acc[im][in][i][jp], aa, bp[in][jp]);
              }
        }
    }

    // epilogue
    #pragma unroll
    for (int im = 0; im < 2; im++)
      #pragma unroll
      for (int i = 0; i < 4; i++) {
          int m = m0 + im * 64 + ty * 4 + i;
          #pragma unroll
          for (int in = 0; in < 2; in++)
            #pragma unroll
            for (int jp = 0; jp < 2; jp++) {
                int n = n0 + in * 64 + tx * 4 + jp * 2;
                float lo, hi;
                UNPK2(lo, hi, acc[im][in][i][jp]);
                if (n < N) {
                    float v = lo;
                    if (HAS_BIAS) v += bias[n];
                    if (HAS_RES)  v += res[(size_t)m * N + n];
                    C[(size_t)m * N + n] = v;
                }
                if (n + 1 < N) {
                    float v = hi;
                    if (HAS_BIAS) v += bias[n + 1];
                    if (HAS_RES)  v += res[(size_t)m * N + n + 1];
                    C[(size_t)m * N + n + 1] = v;
                }
            }
      }
}

// ---------------------------------------------------------------------------
// Row softmax over 4096 floats, one block per row, fully register-resident
// (16 floats/thread), in-place.
// ---------------------------------------------------------------------------
__global__ __launch_bounds__(256)
void softmax_kernel(float* __restrict__ S)
{
    float* row = S + (size_t)blockIdx.x * NPIX;
    const int t = threadIdx.x;

    float4 v[4];
    #pragma unroll
    for (int i = 0; i < 4; i++)
        v[i] = reinterpret_cast<float4*>(row)[t + 256 * i];

    float mx = -3.4e38f;
    #pragma unroll
    for (int i = 0; i < 4; i++)
        mx = fmaxf(mx, fmaxf(fmaxf(v[i].x, v[i].y), fmaxf(v[i].z, v[i].w)));
    #pragma unroll
    for (int o = 16; o > 0; o >>= 1)
        mx = fmaxf(mx, __shfl_xor_sync(0xffffffffu, mx, o));

    __shared__ float red[8];
    if ((t & 31) == 0) red[t >> 5] = mx;
    __syncthreads();
    mx = red[0];
    #pragma unroll
    for (int i = 1; i < 8; i++) mx = fmaxf(mx, red[i]);

    float sum = 0.f;
    #pragma unroll
    for (int i = 0; i < 4; i++) {
        v[i].x = expf(v[i].x - mx); sum += v[i].x;
        v[i].y = expf(v[i].y - mx); sum += v[i].y;
        v[i].z = expf(v[i].z - mx); sum += v[i].z;
        v[i].w = expf(v[i].w - mx); sum += v[i].w;
    }
    #pragma unroll
    for (int o = 16; o > 0; o >>= 1)
        sum += __shfl_xor_sync(0xffffffffu, sum, o);
    __syncthreads();   // all reads of red (max phase) done before reuse
    if ((t & 31) == 0) red[t >> 5] = sum;
    __syncthreads();
    sum = 0.f;
    #pragma unroll
    for (int i = 0; i < 8; i++) sum += red[i];

    float inv = 1.0f / sum;
    #pragma unroll
    for (int i = 0; i < 4; i++) {
        v[i].x *= inv; v[i].y *= inv; v[i].z *= inv; v[i].w *= inv;
        reinterpret_cast<float4*>(row)[t + 256 * i] = v[i];
    }
}

// ---------------------------------------------------------------------------
extern "C" void kernel_launch(void* const* d_in, const int* in_sizes, int n_in,
                              void* d_out, int out_size)
{
    (void)in_sizes; (void)n_in; (void)out_size;
    const float* x  = (const float*)d_in[0];
    const float* Wf = (const float*)d_in[1];
    const float* bf = (const float*)d_in[2];
    const float* Wg = (const float*)d_in[3];
    const float* bg = (const float*)d_in[4];
    const float* Wh = (const float*)d_in[5];
    const float* bh = (const float*)d_in[6];
    const float* Wv = (const float*)d_in[7];
    const float* bv = (const float*)d_in[8];
    float* out = (float*)d_out;

    float *pf, *pg, *phm, *po, *ps;
    cudaGetSymbolAddress((void**)&pf,  g_f);
    cudaGetSymbolAddress((void**)&pg,  g_g);
    cudaGetSymbolAddress((void**)&phm, g_hm);
    cudaGetSymbolAddress((void**)&po,  g_o);
    cudaGetSymbolAddress((void**)&ps,  g_s);

    dim3 blk(256);

    // Projections: f, g (N=32) and hm (N=256), all M=16384, K=256, unbatched
    sgemm_kernel<false, true, false><<<dim3(1, MROWS / 128, 1), blk>>>(
        x, Wf, pf, bf, nullptr, MROWS, CKDIM, CDIM, 0, 0, 0);
    sgemm_kernel<false, true, false><<<dim3(1, MROWS / 128, 1), blk>>>(
        x, Wg, pg, bg, nullptr, MROWS, CKDIM, CDIM, 0, 0, 0);
    sgemm_kernel<false, true, false><<<dim3(CDIM / 128, MROWS / 128, 1), blk>>>(
        x, Wh, phm, bh, nullptr, MROWS, CDIM, CDIM, 0, 0, 0);

    // s[b] = g[b] @ f[b]^T   [4096,4096], K=32, batched over 4
    sgemm_kernel<true, false, false><<<dim3(NPIX / 128, NPIX / 128, BATCH), blk>>>(
        pg, pf, ps, nullptr, nullptr, NPIX, NPIX, CKDIM,
        (long long)NPIX * CKDIM, (long long)NPIX * CKDIM, (long long)NPIX * NPIX);

    // beta = softmax(s) in-place, one block per row
    softmax_kernel<<<dim3(BATCH * NPIX), blk>>>(ps);

    // o[b] = beta[b] @ hm[b]   [4096,256], K=4096, batched over 4
    sgemm_kernel<false, false, false><<<dim3(CDIM / 128, NPIX / 128, BATCH), blk>>>(
        ps, phm, po, nullptr, nullptr, NPIX, CDIM, NPIX,
        (long long)NPIX * NPIX, (long long)NPIX * CDIM, (long long)NPIX * CDIM);

    // out = x + o @ Wv + bv   M=16384, K=256, unbatched, residual epilogue
    sgemm_kernel<false, true, true><<<dim3(CDIM / 128, MROWS / 128, 1), blk>>>(
        po, Wv, out, bv, x, MROWS, CDIM, CDIM, 0, 0, 0);
}

// round 7
// speedup vs baseline: 1.6700x; 1.6700x over previous
#include <cuda_runtime.h>
#include <cuda_bf16.h>
#include <cstdint>

// ---------------------------------------------------------------------------
// SelfAttention (SAGAN-style), B=4, N=4096, C=256, Ck=32.
//   f,g,hm projections + s-GEMM + v-proj: fp32 FFMA2 SGEMM (packed fma.rn.f32x2)
//   o = softmax(g f^T) @ hm: mma.sync m16n8k16 bf16 split (hi/lo, 3 terms),
//     fp32 register accumulate, cp.async double-buffered smem pipeline.
//   (tcgen05 is NOT available: harness compiles via compute_103 (no 'a'),
//    which rejects tcgen05 PTX. mma.sync/ldmatrix/cp.async are baseline PTX.)
// ---------------------------------------------------------------------------

#define BATCH 4
#define NPIX  4096
#define CDIM  256
#define CKDIM 32
#define MROWS (BATCH * NPIX)   // 16384

// Scratch (static __device__: no allocation anywhere)
static __device__ float g_f [MROWS * CKDIM];                     //  2 MB
static __device__ float g_g [MROWS * CKDIM];                     //  2 MB
static __device__ float g_hm[MROWS * CDIM];                      // 16 MB
static __device__ float g_o [MROWS * CDIM];                      // 16 MB
static __device__ float g_s [(size_t)BATCH * NPIX * NPIX];       // 256 MB fp32 scores
static __device__ __nv_bfloat16 g_bh[(size_t)BATCH * NPIX * NPIX];  // 128 MB beta hi
static __device__ __nv_bfloat16 g_bl[(size_t)BATCH * NPIX * NPIX];  // 128 MB beta lo
static __device__ __nv_bfloat16 g_th[(size_t)BATCH * CDIM * NPIX];  // 8 MB hm^T hi
static __device__ __nv_bfloat16 g_tl[(size_t)BATCH * CDIM * NPIX];  // 8 MB hm^T lo

// --- packed f32x2 helpers ---------------------------------------------------
#define FMA2(c, a, b) \
    asm("fma.rn.f32x2 %0, %1, %2, %0;" : "+l"(c) : "l"(a), "l"(b))
#define DUP2(d, s) \
    asm("mov.b64 %0, {%1, %1};" : "=l"(d) : "f"(s))
#define UNPK2(lo, hi, p) \
    asm("mov.b64 {%0, %1}, %2;" : "=f"(lo), "=f"(hi) : "l"(p))

// --- mma.sync / ldmatrix / cp.async helpers (baseline PTX, sm_80+) ----------
__device__ __forceinline__ uint32_t smem_u32(const void* p) {
    uint32_t a;
    asm("{ .reg .u64 t; cvta.to.shared.u64 t, %1; cvt.u32.u64 %0, t; }"
        : "=r"(a) : "l"(p));
    return a;
}

#define SWZ128(off) ((off) ^ (((off) >> 3) & 0x70u))

#define LDSM4(r, addr) \
    asm volatile("ldmatrix.sync.aligned.m8n8.x4.shared.b16 {%0,%1,%2,%3}, [%4];" \
        : "=r"((r)[0]), "=r"((r)[1]), "=r"((r)[2]), "=r"((r)[3]) : "r"(addr))

#define MMA16816(d, a, b0, b1) \
    asm volatile("mma.sync.aligned.m16n8k16.row.col.f32.bf16.bf16.f32 " \
        "{%0,%1,%2,%3}, {%4,%5,%6,%7}, {%8,%9}, {%0,%1,%2,%3};" \
        : "+f"((d)[0]), "+f"((d)[1]), "+f"((d)[2]), "+f"((d)[3]) \
        : "r"((a)[0]), "r"((a)[1]), "r"((a)[2]), "r"((a)[3]), "r"(b0), "r"(b1))

#define CP16(smaddr, gptr) \
    asm volatile("cp.async.cg.shared.global [%0], [%1], 16;" \
        :: "r"(smaddr), "l"(gptr))
#define CP_COMMIT() asm volatile("cp.async.commit_group;" ::: "memory")
#define CP_WAIT1()  asm volatile("cp.async.wait_group 1;" ::: "memory")
#define CP_WAIT0()  asm volatile("cp.async.wait_group 0;" ::: "memory")

// ---------------------------------------------------------------------------
// FFMA2 SGEMM (proven in R5): C = A @ op(B) (+bias)(+res)
// ---------------------------------------------------------------------------
template<bool TRANS_B, bool HAS_BIAS, bool HAS_RES>
__global__ __launch_bounds__(256, 2)
void sgemm_kernel(const float* __restrict__ A, const float* __restrict__ B,
                  float* __restrict__ C,
                  const float* __restrict__ bias, const float* __restrict__ res,
                  int M, int N, int K,
                  long long sA, long long sB, long long sC)
{
    __shared__ float As[8][132];
    __shared__ float Bs[8][132];

    A += (size_t)blockIdx.z * sA;
    B += (size_t)blockIdx.z * sB;
    C += (size_t)blockIdx.z * sC;

    const int m0 = blockIdx.y * 128;
    const int n0 = blockIdx.x * 128;
    const int t  = threadIdx.x;

    const int a_row  = t >> 1;
    const int a_koff = (t & 1) * 4;
    const int b_kr   = t >> 5;
    const int b_nc   = (t & 31) * 4;

    const int tx = t & 15;
    const int ty = t >> 4;

    unsigned long long acc[2][2][4][2];
    #pragma unroll
    for (int im = 0; im < 2; im++)
      #pragma unroll
      for (int in = 0; in < 2; in++)
        #pragma unroll
        for (int i = 0; i < 4; i++)
          #pragma unroll
          for (int jp = 0; jp < 2; jp++)
            acc[im][in][i][jp] = 0ULL;

    for (int k0 = 0; k0 < K; k0 += 8) {
        float4 av = *(const float4*)(A + (size_t)(m0 + a_row) * K + (k0 + a_koff));
        float4 bv;
        if (TRANS_B) {
            int n = n0 + a_row;
            bv = (n < N) ? *(const float4*)(B + (size_t)n * K + (k0 + a_koff))
                         : make_float4(0.f, 0.f, 0.f, 0.f);
        } else {
            int n = n0 + b_nc;
            bv = (n < N) ? *(const float4*)(B + (size_t)(k0 + b_kr) * N + n)
                         : make_float4(0.f, 0.f, 0.f, 0.f);
        }
        __syncthreads();
        As[a_koff + 0][a_row] = av.x;
        As[a_koff + 1][a_row] = av.y;
        As[a_koff + 2][a_row] = av.z;
        As[a_koff + 3][a_row] = av.w;
        if (TRANS_B) {
            Bs[a_koff + 0][a_row] = bv.x;
            Bs[a_koff + 1][a_row] = bv.y;
            Bs[a_koff + 2][a_row] = bv.z;
            Bs[a_koff + 3][a_row] = bv.w;
        } else {
            *(float4*)&Bs[b_kr][b_nc] = bv;
        }
        __syncthreads();

        #pragma unroll
        for (int kk = 0; kk < 8; kk++) {
            float4 a0 = *(const float4*)&As[kk][ty * 4];
            float4 a1 = *(const float4*)&As[kk][64 + ty * 4];
            ulonglong2 b0 = *(const ulonglong2*)&Bs[kk][tx * 4];
            ulonglong2 b1 = *(const ulonglong2*)&Bs[kk][64 + tx * 4];
            float am[2][4] = {{a0.x, a0.y, a0.z, a0.w},
                              {a1.x, a1.y, a1.z, a1.w}};
            unsigned long long bp[2][2] = {{b0.x, b0.y}, {b1.x, b1.y}};
            #pragma unroll
            for (int im = 0; im < 2; im++)
              #pragma unroll
              for (int i = 0; i < 4; i++) {
                  unsigned long long aa;
                  DUP2(aa, am[im][i]);
                  #pragma unroll
                  for (int in = 0; in < 2; in++)
                    #pragma unroll
                    for (int jp = 0; jp < 2; jp++)
                        FMA2(acc[im][in][i][jp], aa, bp[in][jp]);
              }
        }
    }

    #pragma unroll
    for (int im = 0; im < 2; im++)
      #pragma unroll
      for (int i = 0; i < 4; i++) {
          int m = m0 + im * 64 + ty * 4 + i;
          #pragma unroll
          for (int in = 0; in < 2; in++)
            #pragma unroll
            for (int jp = 0; jp < 2; jp++) {
                int n = n0 + in * 64 + tx * 4 + jp * 2;
                float lo, hi;
                UNPK2(lo, hi, acc[im][in][i][jp]);
                if (n < N) {
                    float v = lo;
                    if (HAS_BIAS) v += bias[n];
                    if (HAS_RES)  v += res[(size_t)m * N + n];
                    C[(size_t)m * N + n] = v;
                }
                if (n + 1 < N) {
                    float v = hi;
                    if (HAS_BIAS) v += bias[n + 1];
                    if (HAS_RES)  v += res[(size_t)m * N + n + 1];
                    C[(size_t)m * N + n + 1] = v;
                }
            }
      }
}

// ---------------------------------------------------------------------------
// Softmax over 4096-row, emitting split-bf16 beta (hi + lo) directly.
// ---------------------------------------------------------------------------
__global__ __launch_bounds__(256)
void softmax_kernel(const float* __restrict__ S,
                    __nv_bfloat16* __restrict__ BH,
                    __nv_bfloat16* __restrict__ BL)
{
    const size_t base = (size_t)blockIdx.x * NPIX;
    const float* row = S + base;
    const int t = threadIdx.x;

    float4 v[4];
    #pragma unroll
    for (int i = 0; i < 4; i++)
        v[i] = reinterpret_cast<const float4*>(row)[t + 256 * i];

    float mx = -3.4e38f;
    #pragma unroll
    for (int i = 0; i < 4; i++)
        mx = fmaxf(mx, fmaxf(fmaxf(v[i].x, v[i].y), fmaxf(v[i].z, v[i].w)));
    #pragma unroll
    for (int o = 16; o > 0; o >>= 1)
        mx = fmaxf(mx, __shfl_xor_sync(0xffffffffu, mx, o));

    __shared__ float red[8];
    if ((t & 31) == 0) red[t >> 5] = mx;
    __syncthreads();
    mx = red[0];
    #pragma unroll
    for (int i = 1; i < 8; i++) mx = fmaxf(mx, red[i]);

    float sum = 0.f;
    #pragma unroll
    for (int i = 0; i < 4; i++) {
        v[i].x = expf(v[i].x - mx); sum += v[i].x;
        v[i].y = expf(v[i].y - mx); sum += v[i].y;
        v[i].z = expf(v[i].z - mx); sum += v[i].z;
        v[i].w = expf(v[i].w - mx); sum += v[i].w;
    }
    #pragma unroll
    for (int o = 16; o > 0; o >>= 1)
        sum += __shfl_xor_sync(0xffffffffu, sum, o);
    __syncthreads();
    if ((t & 31) == 0) red[t >> 5] = sum;
    __syncthreads();
    sum = 0.f;
    #pragma unroll
    for (int i = 0; i < 8; i++) sum += red[i];

    float inv = 1.0f / sum;
    #pragma unroll
    for (int i = 0; i < 4; i++) {
        float p[4] = {v[i].x * inv, v[i].y * inv, v[i].z * inv, v[i].w * inv};
        __nv_bfloat162 h01, h23, l01, l23;
        __nv_bfloat16 h;
        h = __float2bfloat16(p[0]); h01.x = h; l01.x = __float2bfloat16(p[0] - __bfloat162float(h));
        h = __float2bfloat16(p[1]); h01.y = h; l01.y = __float2bfloat16(p[1] - __bfloat162float(h));
        h = __float2bfloat16(p[2]); h23.x = h; l23.x = __float2bfloat16(p[2] - __bfloat162float(h));
        h = __float2bfloat16(p[3]); h23.y = h; l23.y = __float2bfloat16(p[3] - __bfloat162float(h));
        size_t off = base + (size_t)(t + 256 * i) * 4;
        reinterpret_cast<__nv_bfloat162*>(BH + off)[0] = h01;
        reinterpret_cast<__nv_bfloat162*>(BH + off)[1] = h23;
        reinterpret_cast<__nv_bfloat162*>(BL + off)[0] = l01;
        reinterpret_cast<__nv_bfloat162*>(BL + off)[1] = l23;
    }
}

// ---------------------------------------------------------------------------
// Transpose + split-bf16: hm [b][4096][256] f32 -> hm^T hi/lo [b][256][4096]
// ---------------------------------------------------------------------------
__global__ __launch_bounds__(256)
void hmt_kernel(const float* __restrict__ HM,
                __nv_bfloat16* __restrict__ TH,
                __nv_bfloat16* __restrict__ TL)
{
    __shared__ float tile[32][33];
    const int b = blockIdx.z;
    const int m0 = blockIdx.x * 32;
    const int c0 = blockIdx.y * 32;
    const int tx = threadIdx.x;       // 0..31
    const int ty = threadIdx.y;       // 0..7

    #pragma unroll
    for (int j = 0; j < 4; j++) {
        int mr = ty + 8 * j;
        tile[mr][tx] = HM[((size_t)(b * NPIX + m0 + mr)) * CDIM + c0 + tx];
    }
    __syncthreads();
    #pragma unroll
    for (int j = 0; j < 4; j++) {
        int cr = ty + 8 * j;
        float vv = tile[tx][cr];
        __nv_bfloat16 h = __float2bfloat16(vv);
        size_t idx = ((size_t)(b * CDIM + c0 + cr)) * NPIX + m0 + tx;
        TH[idx] = h;
        TL[idx] = __float2bfloat16(vv - __bfloat162float(h));
    }
}

// ---------------------------------------------------------------------------
// o-GEMM via mma.sync split-bf16:
//   o[b][4096][256] = beta[b] @ hm[b]
//   A = beta hi/lo [M=4096, K=4096] row-major bf16
//   B = hm^T hi/lo [N=256,  K=4096] row-major bf16 (= B col-major for row.col)
// CTA tile 128x128, K chunks of 64, double-buffered cp.async, SW128 swizzle.
// 8 warps (4x2): warp tile 32x64 = 2 m16-tiles x 8 n8-tiles.
// 3 mma terms per tile position: Ah*Bh + Ah*Bl + Al*Bh (drop lo*lo ~ 2^-18).
// Grid (32, 2, 4), 256 threads, 1 CTA/SM (128KB smem).
// ---------------------------------------------------------------------------
#define OKC      64
#define ONCHUNK  (NPIX / OKC)            // 64
#define OARR     (128 * 128)             // 16KB: one 128-row x 128B array
#define O_AH     0
#define O_AL     (OARR)
#define O_BH     (2 * OARR)
#define O_BL     (3 * OARR)
#define OSTAGE   (4 * OARR)              // 64KB
#define OSMEM    (2 * OSTAGE)            // 128KB

__global__ void __launch_bounds__(256, 1)
o_mma_kernel(const __nv_bfloat16* __restrict__ Ah,
             const __nv_bfloat16* __restrict__ Al,
             const __nv_bfloat16* __restrict__ Bh,
             const __nv_bfloat16* __restrict__ Bl,
             float* __restrict__ O)
{
    extern __shared__ __align__(1024) char osm[];

    const int t    = threadIdx.x;
    const int b    = blockIdx.z;
    const int m0   = blockIdx.x * 128;
    const int n0   = blockIdx.y * 128;
    const int lane = t & 31;
    const int wid  = t >> 5;
    const int wm   = wid >> 1;     // 0..3 -> 32-row band
    const int wn   = wid & 1;      // 0..1 -> 64-col band

    const uint32_t smb = smem_u32(osm);

    // per-batch / per-tile base pointers (rows already offset)
    const __nv_bfloat16* pAh = Ah + ((size_t)(b * NPIX + m0)) * NPIX;
    const __nv_bfloat16* pAl = Al + ((size_t)(b * NPIX + m0)) * NPIX;
    const __nv_bfloat16* pBh = Bh + ((size_t)(b * CDIM + n0)) * NPIX;
    const __nv_bfloat16* pBl = Bl + ((size_t)(b * CDIM + n0)) * NPIX;

    // cp.async mapping: 1024 16B-units per array, 4 per thread per array
    const int l_row = t >> 1;          // reused pattern: idx = t + 256*i
    (void)l_row;

    float acc[2][8][4];
    #pragma unroll
    for (int mt = 0; mt < 2; mt++)
      #pragma unroll
      for (int nt = 0; nt < 8; nt++)
        #pragma unroll
        for (int q = 0; q < 4; q++)
            acc[mt][nt][q] = 0.f;

    // ---- stage loader (cp.async, swizzled) ----
    auto load_stage = [&](int s, int c) {
        const uint32_t sb = smb + s * OSTAGE;
        const int k0 = c * OKC;
        #pragma unroll
        for (int i = 0; i < 4; i++) {
            int idx = t + 256 * i;
            int row = idx >> 3;            // 0..127
            int col = idx & 7;             // 16B unit
            uint32_t off = SWZ128((uint32_t)(row * 128 + col * 16));
            const char* gA = (const char*)(pAh + (size_t)row * NPIX + k0) + col * 16;
            CP16(sb + O_AH + off, gA);
            const char* gA2 = (const char*)(pAl + (size_t)row * NPIX + k0) + col * 16;
            CP16(sb + O_AL + off, gA2);
            const char* gB = (const char*)(pBh + (size_t)row * NPIX + k0) + col * 16;
            CP16(sb + O_BH + off, gB);
            const char* gB2 = (const char*)(pBl + (size_t)row * NPIX + k0) + col * 16;
            CP16(sb + O_BL + off, gB2);
        }
    };

    load_stage(0, 0);
    CP_COMMIT();

    for (int c = 0; c < ONCHUNK; ++c) {
        if (c + 1 < ONCHUNK) {
            load_stage((c + 1) & 1, c + 1);
            CP_COMMIT();
            CP_WAIT1();
        } else {
            CP_WAIT0();
        }
        __syncthreads();

        const uint32_t sb  = smb + (c & 1) * OSTAGE;
        const uint32_t sAh = sb + O_AH, sAl = sb + O_AL;
        const uint32_t sBh = sb + O_BH, sBl = sb + O_BL;

        #pragma unroll
        for (int ks = 0; ks < 4; ks++) {
            const uint32_t kbyte = ks * 32 + ((lane >> 4) << 4);

            uint32_t afh[2][4], afl[2][4];
            #pragma unroll
            for (int mt = 0; mt < 2; mt++) {
                int row = wm * 32 + mt * 16 + (lane & 15);
                uint32_t off = SWZ128((uint32_t)(row * 128) + kbyte);
                LDSM4(afh[mt], sAh + off);
                LDSM4(afl[mt], sAl + off);
            }

            #pragma unroll
            for (int ntp = 0; ntp < 4; ntp++) {
                int row = wn * 64 + ntp * 16 + (lane & 15);
                uint32_t off = SWZ128((uint32_t)(row * 128) + kbyte);
                uint32_t bfh[4], bfl[4];
                LDSM4(bfh, sBh + off);
                LDSM4(bfl, sBl + off);
                #pragma unroll
                for (int h = 0; h < 2; h++) {
                    // ldmatrix x4: m0=rows0-7/k0-7, m1=rows8-15/k0-7,
                    //              m2=rows0-7/k8-15, m3=rows8-15/k8-15
                    uint32_t b0h = h ? bfh[1] : bfh[0];
                    uint32_t b1h = h ? bfh[3] : bfh[2];
                    uint32_t b0l = h ? bfl[1] : bfl[0];
                    uint32_t b1l = h ? bfl[3] : bfl[2];
                    const int nt = ntp * 2 + h;
                    #pragma unroll
                    for (int mt = 0; mt < 2; mt++) {
                        MMA16816(acc[mt][nt], afh[mt], b0h, b1h);
                        MMA16816(acc[mt][nt], afh[mt], b0l, b1l);
                        MMA16816(acc[mt][nt], afl[mt], b0h, b1h);
                    }
                }
            }
        }
        __syncthreads();
    }

    // epilogue: c-frag thread mapping: rows g, g+8; cols 2q, 2q+1
    const int g = lane >> 2;
    const int q = lane & 3;
    #pragma unroll
    for (int mt = 0; mt < 2; mt++) {
        int r0 = m0 + wm * 32 + mt * 16 + g;
        #pragma unroll
        for (int nt = 0; nt < 8; nt++) {
            int col = n0 + wn * 64 + nt * 8 + q * 2;
            float* p0 = O + ((size_t)(b * NPIX + r0)) * CDIM + col;
            float* p1 = O + ((size_t)(b * NPIX + r0 + 8)) * CDIM + col;
            *(float2*)p0 = make_float2(acc[mt][nt][0], acc[mt][nt][1]);
            *(float2*)p1 = make_float2(acc[mt][nt][2], acc[mt][nt][3]);
        }
    }
}

// ---------------------------------------------------------------------------
extern "C" void kernel_launch(void* const* d_in, const int* in_sizes, int n_in,
                              void* d_out, int out_size)
{
    (void)in_sizes; (void)n_in; (void)out_size;
    const float* x  = (const float*)d_in[0];
    const float* Wf = (const float*)d_in[1];
    const float* bf = (const float*)d_in[2];
    const float* Wg = (const float*)d_in[3];
    const float* bg = (const float*)d_in[4];
    const float* Wh = (const float*)d_in[5];
    const float* bh = (const float*)d_in[6];
    const float* Wv = (const float*)d_in[7];
    const float* bv = (const float*)d_in[8];
    float* out = (float*)d_out;

    float *pf, *pg, *phm, *po, *ps;
    __nv_bfloat16 *pbh, *pbl, *pth, *ptl;
    cudaGetSymbolAddress((void**)&pf,  g_f);
    cudaGetSymbolAddress((void**)&pg,  g_g);
    cudaGetSymbolAddress((void**)&phm, g_hm);
    cudaGetSymbolAddress((void**)&po,  g_o);
    cudaGetSymbolAddress((void**)&ps,  g_s);
    cudaGetSymbolAddress((void**)&pbh, g_bh);
    cudaGetSymbolAddress((void**)&pbl, g_bl);
    cudaGetSymbolAddress((void**)&pth, g_th);
    cudaGetSymbolAddress((void**)&ptl, g_tl);

    cudaFuncSetAttribute(o_mma_kernel,
                         cudaFuncAttributeMaxDynamicSharedMemorySize, OSMEM);

    dim3 blk(256);

    // Projections: f, g (N=32), hm (N=256)
    sgemm_kernel<false, true, false><<<dim3(1, MROWS / 128, 1), blk>>>(
        x, Wf, pf, bf, nullptr, MROWS, CKDIM, CDIM, 0, 0, 0);
    sgemm_kernel<false, true, false><<<dim3(1, MROWS / 128, 1), blk>>>(
        x, Wg, pg, bg, nullptr, MROWS, CKDIM, CDIM, 0, 0, 0);
    sgemm_kernel<false, true, false><<<dim3(CDIM / 128, MROWS / 128, 1), blk>>>(
        x, Wh, phm, bh, nullptr, MROWS, CDIM, CDIM, 0, 0, 0);

    // hm -> hm^T hi/lo bf16
    hmt_kernel<<<dim3(NPIX / 32, CDIM / 32, BATCH), dim3(32, 8)>>>(phm, pth, ptl);

    // s[b] = g[b] @ f[b]^T
    sgemm_kernel<true, false, false><<<dim3(NPIX / 128, NPIX / 128, BATCH), blk>>>(
        pg, pf, ps, nullptr, nullptr, NPIX, NPIX, CKDIM,
        (long long)NPIX * CKDIM, (long long)NPIX * CKDIM, (long long)NPIX * NPIX);

    // beta = softmax(s) -> split bf16
    softmax_kernel<<<dim3(BATCH * NPIX), blk>>>(ps, pbh, pbl);

    // o[b] = beta[b] @ hm[b]  (mma.sync split-bf16)
    o_mma_kernel<<<dim3(NPIX / 128, CDIM / 128, BATCH), blk, OSMEM>>>(
        pbh, pbl, pth, ptl, po);

    // out = x + o @ Wv + bv
    sgemm_kernel<false, true, true><<<dim3(CDIM / 128, MROWS / 128, 1), blk>>>(
        po, Wv, out, bv, x, MROWS, CDIM, CDIM, 0, 0, 0);
}

// round 9
// speedup vs baseline: 2.1547x; 1.2903x over previous
#include <cuda_runtime.h>
#include <cuda_bf16.h>
#include <cstdint>

// ---------------------------------------------------------------------------
// SelfAttention (SAGAN-style), B=4, N=4096, C=256, Ck=32.
// ALL GEMMs now run on mma.sync.m16n8k16 bf16 split (hi/lo, 3 terms, fp32 acc)
// via one generic NT-form kernel (C[m][n] = sum_k A[m][k] B[n][k]):
//   fg proj   : A=x-split,   B=(Wf|Wg)^T-split  -> f,g split (K padded to 64)
//   hm^T proj : A=Wh^T-split, B=x-split          -> hm^T split (bias on rows)
//   s         : A=g-split,   B=f-split (K=64)    -> fp32 scores
//   o         : A=beta-split, B=hm^T-split       -> o split
//   v proj    : A=o-split,   B=Wv^T-split (+bv, +x residual) -> fp32 out
// (tcgen05 unavailable: harness builds via compute_103 (no 'a' suffix);
//  mma.sync/ldmatrix/cp.async are baseline PTX and hit the tensor pipe.)
// ---------------------------------------------------------------------------

#define BATCH 4
#define NPIX  4096
#define CDIM  256
#define CKDIM 32
#define MROWS 16384
#define KPAD  64

typedef __nv_bfloat16 bf16;

// Scratch (static __device__, 16B-aligned for cp.async/float4)
static __device__ __align__(16) bf16 g_xh[MROWS * CDIM];              // 8 MB
static __device__ __align__(16) bf16 g_xl[MROWS * CDIM];              // 8 MB
static __device__ __align__(16) bf16 g_wfgt_h[64 * CDIM];
static __device__ __align__(16) bf16 g_wfgt_l[64 * CDIM];
static __device__ __align__(16) bf16 g_wht_h[CDIM * CDIM];
static __device__ __align__(16) bf16 g_wht_l[CDIM * CDIM];
static __device__ __align__(16) bf16 g_wvt_h[CDIM * CDIM];
static __device__ __align__(16) bf16 g_wvt_l[CDIM * CDIM];
static __device__ __align__(16) bf16 g_fh[MROWS * KPAD];              // 2 MB each
static __device__ __align__(16) bf16 g_fl[MROWS * KPAD];
static __device__ __align__(16) bf16 g_gh[MROWS * KPAD];
static __device__ __align__(16) bf16 g_gl[MROWS * KPAD];
static __device__ __align__(16) bf16 g_th[(size_t)BATCH * CDIM * NPIX];  // 8 MB
static __device__ __align__(16) bf16 g_tl[(size_t)BATCH * CDIM * NPIX];
static __device__ __align__(16) float g_s[(size_t)BATCH * NPIX * NPIX];  // 256 MB
static __device__ __align__(16) bf16 g_bh[(size_t)BATCH * NPIX * NPIX];  // 128 MB
static __device__ __align__(16) bf16 g_bl[(size_t)BATCH * NPIX * NPIX];  // 128 MB
static __device__ __align__(16) bf16 g_oh[MROWS * CDIM];              // 8 MB
static __device__ __align__(16) bf16 g_ol[MROWS * CDIM];

// --- PTX helpers (baseline PTX, proven in R7) -------------------------------
__device__ __forceinline__ uint32_t smem_u32(const void* p) {
    uint32_t a;
    asm("{ .reg .u64 t; cvta.to.shared.u64 t, %1; cvt.u32.u64 %0, t; }"
        : "=r"(a) : "l"(p));
    return a;
}

#define SWZ128(off) ((off) ^ (((off) >> 3) & 0x70u))

#define LDSM4(r, addr) \
    asm volatile("ldmatrix.sync.aligned.m8n8.x4.shared.b16 {%0,%1,%2,%3}, [%4];" \
        : "=r"((r)[0]), "=r"((r)[1]), "=r"((r)[2]), "=r"((r)[3]) : "r"(addr))

#define MMA16816(d, a, b0, b1) \
    asm volatile("mma.sync.aligned.m16n8k16.row.col.f32.bf16.bf16.f32 " \
        "{%0,%1,%2,%3}, {%4,%5,%6,%7}, {%8,%9}, {%0,%1,%2,%3};" \
        : "+f"((d)[0]), "+f"((d)[1]), "+f"((d)[2]), "+f"((d)[3]) \
        : "r"((a)[0]), "r"((a)[1]), "r"((a)[2]), "r"((a)[3]), "r"(b0), "r"(b1))

#define CP16(smaddr, gptr) \
    asm volatile("cp.async.cg.shared.global [%0], [%1], 16;" \
        :: "r"(smaddr), "l"(gptr))
#define CP_COMMIT() asm volatile("cp.async.commit_group;" ::: "memory")
#define CP_WAIT1()  asm volatile("cp.async.wait_group 1;" ::: "memory")
#define CP_WAIT0()  asm volatile("cp.async.wait_group 0;" ::: "memory")

// ---------------------------------------------------------------------------
// x -> split bf16 (hi/lo), elementwise, float4-vectorized
// ---------------------------------------------------------------------------
__global__ __launch_bounds__(256)
void xsplit_kernel(const float* __restrict__ X,
                   bf16* __restrict__ H, bf16* __restrict__ L)
{
    int i = blockIdx.x * 256 + threadIdx.x;      // over MROWS*CDIM/4
    float4 v = reinterpret_cast<const float4*>(X)[i];
    float p[4] = {v.x, v.y, v.z, v.w};
    __nv_bfloat162 h01, h23, l01, l23;
    bf16 h;
    h = __float2bfloat16(p[0]); h01.x = h; l01.x = __float2bfloat16(p[0] - __bfloat162float(h));
    h = __float2bfloat16(p[1]); h01.y = h; l01.y = __float2bfloat16(p[1] - __bfloat162float(h));
    h = __float2bfloat16(p[2]); h23.x = h; l23.x = __float2bfloat16(p[2] - __bfloat162float(h));
    h = __float2bfloat16(p[3]); h23.y = h; l23.y = __float2bfloat16(p[3] - __bfloat162float(h));
    reinterpret_cast<__nv_bfloat162*>(H + (size_t)i * 4)[0] = h01;
    reinterpret_cast<__nv_bfloat162*>(H + (size_t)i * 4)[1] = h23;
    reinterpret_cast<__nv_bfloat162*>(L + (size_t)i * 4)[0] = l01;
    reinterpret_cast<__nv_bfloat162*>(L + (size_t)i * 4)[1] = l23;
}

// ---------------------------------------------------------------------------
// Weight prep: transpose + split. Rows: 0-63 -> (Wf|Wg)^T, 64-319 -> Wh^T,
// 320-575 -> Wv^T. Tiny (576x256), latency-bound.
// ---------------------------------------------------------------------------
__global__ __launch_bounds__(256)
void wprep_kernel(const float* __restrict__ Wf, const float* __restrict__ Wg,
                  const float* __restrict__ Wh, const float* __restrict__ Wv,
                  bf16* __restrict__ FGh, bf16* __restrict__ FGl,
                  bf16* __restrict__ WHh, bf16* __restrict__ WHl,
                  bf16* __restrict__ WVh, bf16* __restrict__ WVl)
{
    int r = blockIdx.x;
    int k = threadIdx.x;
    float w;
    bf16 *ph, *pl;
    int out;
    if (r < 64) {
        w = (r < 32) ? Wf[k * CKDIM + r] : Wg[k * CKDIM + (r - 32)];
        ph = FGh; pl = FGl; out = r * CDIM + k;
    } else if (r < 320) {
        int c = r - 64;
        w = Wh[k * CDIM + c];
        ph = WHh; pl = WHl; out = c * CDIM + k;
    } else {
        int c = r - 320;
        w = Wv[k * CDIM + c];
        ph = WVh; pl = WVl; out = c * CDIM + k;
    }
    bf16 h = __float2bfloat16(w);
    ph[out] = h;
    pl[out] = __float2bfloat16(w - __bfloat162float(h));
}

// ---------------------------------------------------------------------------
// Generic NT GEMM, mma.sync split-bf16 (3 terms), cp.async double buffer.
// C[m][n] = sum_k A[m][k] * B[n][k], K % 64 == 0, M % 128 == 0, N % NT == 0.
// Template:
//   NT   : 128 or 64 (CTA n-tile; m-tile fixed 128)
//   OUT  : 0 = fp32 C0,  1 = split-bf16 (C0=hi, C1=lo)
//   BIAS : 0 none, 1 bias[col], 2 bias[row]
//   RES  : 1 = += resid[row*ldC+col] (fp32)
//   NMAP : 0 plain (z*sC + row*ldC + col)
//          1 hm^T  (col -> batch b=col>>12, nn=col&4095; ((b*256+row)*4096+nn))
//          2 fg    (col<32 -> C0/C1[row*64+col] + zero pad at col+32;
//                   col>=32 -> C2/C3[row*64+col-32] + zero pad; bias/bias2)
// Grid: (M/128, N/NT, batch). 256 threads.
// ---------------------------------------------------------------------------
template<int NT, int OUT, int BIAS, int RES, int NMAP>
__global__ void __launch_bounds__(256, 1)
gemm_nt(const bf16* __restrict__ Ah, const bf16* __restrict__ Al, long long sA,
        const bf16* __restrict__ Bh, const bf16* __restrict__ Bl, long long sB,
        void* __restrict__ C0, void* __restrict__ C1,
        void* __restrict__ C2, void* __restrict__ C3,
        long long sC, int ldC,
        const float* __restrict__ bias, const float* __restrict__ bias2,
        const float* __restrict__ resid, int K)
{
    extern __shared__ __align__(1024) char gsm[];
    constexpr int AHo = 0;
    constexpr int ALo = 128 * 128;
    constexpr int BHo = 2 * 128 * 128;
    constexpr int BLo = BHo + NT * 128;
    constexpr int STG = BHo + 2 * NT * 128;

    const int t    = threadIdx.x;
    const int lane = t & 31;
    const int wid  = t >> 5;
    const int wm   = wid >> 1;
    const int wn   = wid & 1;
    const int m0   = blockIdx.x * 128;
    const int n0   = blockIdx.y * NT;
    const int z    = blockIdx.z;

    const uint32_t smb = smem_u32(gsm);
    const bf16* pAh = Ah + (size_t)z * sA + (size_t)m0 * K;
    const bf16* pAl = Al + (size_t)z * sA + (size_t)m0 * K;
    const bf16* pBh = Bh + (size_t)z * sB + (size_t)n0 * K;
    const bf16* pBl = Bl + (size_t)z * sB + (size_t)n0 * K;

    float acc[2][NT / 16][4];
    #pragma unroll
    for (int mt = 0; mt < 2; mt++)
      #pragma unroll
      for (int nt = 0; nt < NT / 16; nt++)
        #pragma unroll
        for (int q = 0; q < 4; q++)
            acc[mt][nt][q] = 0.f;

    auto load_stage = [&](int s, int c) {
        const uint32_t sb = smb + s * STG;
        const int k0 = c * 64;
        #pragma unroll
        for (int i = 0; i < 4; i++) {
            int idx = t + 256 * i;
            int row = idx >> 3, col = idx & 7;
            uint32_t off = SWZ128((uint32_t)(row * 128 + col * 16));
            CP16(sb + AHo + off, (const char*)(pAh + (size_t)row * K + k0) + col * 16);
            CP16(sb + ALo + off, (const char*)(pAl + (size_t)row * K + k0) + col * 16);
        }
        #pragma unroll
        for (int i = 0; i < NT / 32; i++) {
            int idx = t + 256 * i;
            int row = idx >> 3, col = idx & 7;
            uint32_t off = SWZ128((uint32_t)(row * 128 + col * 16));
            CP16(sb + BHo + off, (const char*)(pBh + (size_t)row * K + k0) + col * 16);
            CP16(sb + BLo + off, (const char*)(pBl + (size_t)row * K + k0) + col * 16);
        }
    };

    const int chunks = K >> 6;
    load_stage(0, 0);
    CP_COMMIT();

    for (int c = 0; c < chunks; ++c) {
        if (c + 1 < chunks) {
            load_stage((c + 1) & 1, c + 1);
            CP_COMMIT();
            CP_WAIT1();
        } else {
            CP_WAIT0();
        }
        __syncthreads();

        const uint32_t sb  = smb + (c & 1) * STG;
        const uint32_t sAh = sb + AHo, sAl = sb + ALo;
        const uint32_t sBh = sb + BHo, sBl = sb + BLo;

        #pragma unroll
        for (int ks = 0; ks < 4; ks++) {
            const uint32_t kbyte = ks * 32 + ((lane >> 4) << 4);

            uint32_t afh[2][4], afl[2][4];
            #pragma unroll
            for (int mt = 0; mt < 2; mt++) {
                int row = wm * 32 + mt * 16 + (lane & 15);
                uint32_t off = SWZ128((uint32_t)(row * 128) + kbyte);
                LDSM4(afh[mt], sAh + off);
                LDSM4(afl[mt], sAl + off);
            }

            #pragma unroll
            for (int ntp = 0; ntp < NT / 32; ntp++) {
                int row = wn * (NT / 2) + ntp * 16 + (lane & 15);
                uint32_t off = SWZ128((uint32_t)(row * 128) + kbyte);
                uint32_t bfh[4], bfl[4];
                LDSM4(bfh, sBh + off);
                LDSM4(bfl, sBl + off);
                #pragma unroll
                for (int h = 0; h < 2; h++) {
                    uint32_t b0h = h ? bfh[1] : bfh[0];
                    uint32_t b1h = h ? bfh[3] : bfh[2];
                    uint32_t b0l = h ? bfl[1] : bfl[0];
                    uint32_t b1l = h ? bfl[3] : bfl[2];
                    const int nt = ntp * 2 + h;
                    #pragma unroll
                    for (int mt = 0; mt < 2; mt++) {
                        MMA16816(acc[mt][nt], afh[mt], b0h, b1h);
                        MMA16816(acc[mt][nt], afh[mt], b0l, b1l);
                        MMA16816(acc[mt][nt], afl[mt], b0h, b1h);
                    }
                }
            }
        }
        __syncthreads();
    }

    // ---- epilogue ----
    const int g = lane >> 2;
    const int q = lane & 3;

    auto store2 = [&](int rg, int cg, float v0, float v1) {
        if constexpr (BIAS == 1) { v0 += bias[cg]; v1 += bias[cg + 1]; }
        if constexpr (BIAS == 2) { float bb = bias[rg]; v0 += bb; v1 += bb; }

        if constexpr (NMAP == 2) {
            bool isf = (cg < 32);
            float b0 = isf ? bias[cg]  : bias2[cg - 32];
            float b1 = isf ? bias[cg + 1] : bias2[cg - 31];
            v0 += b0; v1 += b1;
            bf16 h0 = __float2bfloat16(v0);
            bf16 h1 = __float2bfloat16(v1);
            __nv_bfloat162 hp; hp.x = h0; hp.y = h1;
            __nv_bfloat162 lp;
            lp.x = __float2bfloat16(v0 - __bfloat162float(h0));
            lp.y = __float2bfloat16(v1 - __bfloat162float(h1));
            __nv_bfloat162 zp; zp.x = __float2bfloat16(0.f); zp.y = zp.x;
            size_t rowb = (size_t)rg * KPAD;
            if (isf) {
                *(__nv_bfloat162*)((bf16*)C0 + rowb + cg) = hp;
                *(__nv_bfloat162*)((bf16*)C1 + rowb + cg) = lp;
                *(__nv_bfloat162*)((bf16*)C0 + rowb + cg + 32) = zp;
                *(__nv_bfloat162*)((bf16*)C1 + rowb + cg + 32) = zp;
            } else {
                *(__nv_bfloat162*)((bf16*)C2 + rowb + cg - 32) = hp;
                *(__nv_bfloat162*)((bf16*)C3 + rowb + cg - 32) = lp;
                *(__nv_bfloat162*)((bf16*)C2 + rowb + cg) = zp;
                *(__nv_bfloat162*)((bf16*)C3 + rowb + cg) = zp;
            }
        } else if constexpr (OUT == 0) {
            size_t off = (size_t)z * sC + (size_t)rg * ldC + cg;
            if constexpr (RES) {
                v0 += resid[(size_t)rg * ldC + cg];
                v1 += resid[(size_t)rg * ldC + cg + 1];
            }
            *(float2*)((float*)C0 + off) = make_float2(v0, v1);
        } else {
            size_t off;
            if constexpr (NMAP == 1) {
                int bb = cg >> 12, nn = cg & 4095;
                off = ((size_t)(bb * CDIM + rg)) * NPIX + nn;
            } else {
                off = (size_t)z * sC + (size_t)rg * ldC + cg;
            }
            bf16 h0 = __float2bfloat16(v0);
            bf16 h1 = __float2bfloat16(v1);
            __nv_bfloat162 hp; hp.x = h0; hp.y = h1;
            __nv_bfloat162 lp;
            lp.x = __float2bfloat16(v0 - __bfloat162float(h0));
            lp.y = __float2bfloat16(v1 - __bfloat162float(h1));
            *(__nv_bfloat162*)((bf16*)C0 + off) = hp;
            *(__nv_bfloat162*)((bf16*)C1 + off) = lp;
        }
    };

    #pragma unroll
    for (int mt = 0; mt < 2; mt++) {
        #pragma unroll
        for (int nt = 0; nt < NT / 16; nt++) {
            int rg = m0 + wm * 32 + mt * 16 + g;
            int cg = n0 + wn * (NT / 2) + nt * 8 + q * 2;
            store2(rg,     cg, acc[mt][nt][0], acc[mt][nt][1]);
            store2(rg + 8, cg, acc[mt][nt][2], acc[mt][nt][3]);
        }
    }
}

// ---------------------------------------------------------------------------
// Softmax over 4096-row, emitting split-bf16 beta (hi + lo).  (unchanged)
// ---------------------------------------------------------------------------
__global__ __launch_bounds__(256)
void softmax_kernel(const float* __restrict__ S,
                    bf16* __restrict__ BH, bf16* __restrict__ BL)
{
    const size_t base = (size_t)blockIdx.x * NPIX;
    const float* row = S + base;
    const int t = threadIdx.x;

    float4 v[4];
    #pragma unroll
    for (int i = 0; i < 4; i++)
        v[i] = reinterpret_cast<const float4*>(row)[t + 256 * i];

    float mx = -3.4e38f;
    #pragma unroll
    for (int i = 0; i < 4; i++)
        mx = fmaxf(mx, fmaxf(fmaxf(v[i].x, v[i].y), fmaxf(v[i].z, v[i].w)));
    #pragma unroll
    for (int o = 16; o > 0; o >>= 1)
        mx = fmaxf(mx, __shfl_xor_sync(0xffffffffu, mx, o));

    __shared__ float red[8];
    if ((t & 31) == 0) red[t >> 5] = mx;
    __syncthreads();
    mx = red[0];
    #pragma unroll
    for (int i = 1; i < 8; i++) mx = fmaxf(mx, red[i]);

    float sum = 0.f;
    #pragma unroll
    for (int i = 0; i < 4; i++) {
        v[i].x = expf(v[i].x - mx); sum += v[i].x;
        v[i].y = expf(v[i].y - mx); sum += v[i].y;
        v[i].z = expf(v[i].z - mx); sum += v[i].z;
        v[i].w = expf(v[i].w - mx); sum += v[i].w;
    }
    #pragma unroll
    for (int o = 16; o > 0; o >>= 1)
        sum += __shfl_xor_sync(0xffffffffu, sum, o);
    __syncthreads();
    if ((t & 31) == 0) red[t >> 5] = sum;
    __syncthreads();
    sum = 0.f;
    #pragma unroll
    for (int i = 0; i < 8; i++) sum += red[i];

    float inv = 1.0f / sum;
    #pragma unroll
    for (int i = 0; i < 4; i++) {
        float p[4] = {v[i].x * inv, v[i].y * inv, v[i].z * inv, v[i].w * inv};
        __nv_bfloat162 h01, h23, l01, l23;
        bf16 h;
        h = __float2bfloat16(p[0]); h01.x = h; l01.x = __float2bfloat16(p[0] - __bfloat162float(h));
        h = __float2bfloat16(p[1]); h01.y = h; l01.y = __float2bfloat16(p[1] - __bfloat162float(h));
        h = __float2bfloat16(p[2]); h23.x = h; l23.x = __float2bfloat16(p[2] - __bfloat162float(h));
        h = __float2bfloat16(p[3]); h23.y = h; l23.y = __float2bfloat16(p[3] - __bfloat162float(h));
        size_t off = base + (size_t)(t + 256 * i) * 4;
        reinterpret_cast<__nv_bfloat162*>(BH + off)[0] = h01;
        reinterpret_cast<__nv_bfloat162*>(BH + off)[1] = h23;
        reinterpret_cast<__nv_bfloat162*>(BL + off)[0] = l01;
        reinterpret_cast<__nv_bfloat162*>(BL + off)[1] = l23;
    }
}

// ---------------------------------------------------------------------------
extern "C" void kernel_launch(void* const* d_in, const int* in_sizes, int n_in,
                              void* d_out, int out_size)
{
    (void)in_sizes; (void)n_in; (void)out_size;
    const float* x  = (const float*)d_in[0];
    const float* Wf = (const float*)d_in[1];
    const float* bf = (const float*)d_in[2];
    const float* Wg = (const float*)d_in[3];
    const float* bg = (const float*)d_in[4];
    const float* Wh = (const float*)d_in[5];
    const float* bh = (const float*)d_in[6];
    const float* Wv = (const float*)d_in[7];
    const float* bv = (const float*)d_in[8];
    float* out = (float*)d_out;

    bf16 *xh, *xl, *fgth, *fgtl, *whth, *whtl, *wvth, *wvtl;
    bf16 *fh, *fl, *gh, *gl, *th, *tl, *bbh, *bbl, *oh, *ol;
    float* ps;
    cudaGetSymbolAddress((void**)&xh,   g_xh);
    cudaGetSymbolAddress((void**)&xl,   g_xl);
    cudaGetSymbolAddress((void**)&fgth, g_wfgt_h);
    cudaGetSymbolAddress((void**)&fgtl, g_wfgt_l);
    cudaGetSymbolAddress((void**)&whth, g_wht_h);
    cudaGetSymbolAddress((void**)&whtl, g_wht_l);
    cudaGetSymbolAddress((void**)&wvth, g_wvt_h);
    cudaGetSymbolAddress((void**)&wvtl, g_wvt_l);
    cudaGetSymbolAddress((void**)&fh,   g_fh);
    cudaGetSymbolAddress((void**)&fl,   g_fl);
    cudaGetSymbolAddress((void**)&gh,   g_gh);
    cudaGetSymbolAddress((void**)&gl,   g_gl);
    cudaGetSymbolAddress((void**)&th,   g_th);
    cudaGetSymbolAddress((void**)&tl,   g_tl);
    cudaGetSymbolAddress((void**)&ps,   g_s);
    cudaGetSymbolAddress((void**)&bbh,  g_bh);
    cudaGetSymbolAddress((void**)&bbl,  g_bl);
    cudaGetSymbolAddress((void**)&oh,   g_oh);
    cudaGetSymbolAddress((void**)&ol,   g_ol);

    const int SM128 = 2 * (2 * 128 * 128 + 2 * 128 * 128);   // 131072
    const int SM64  = 2 * (2 * 128 * 128 + 2 * 64 * 128);    //  98304
    cudaFuncSetAttribute(gemm_nt<64, 1, 0, 0, 2>,
                         cudaFuncAttributeMaxDynamicSharedMemorySize, SM64);
    cudaFuncSetAttribute(gemm_nt<128, 1, 2, 0, 1>,
                         cudaFuncAttributeMaxDynamicSharedMemorySize, SM128);
    cudaFuncSetAttribute(gemm_nt<128, 0, 0, 0, 0>,
                         cudaFuncAttributeMaxDynamicSharedMemorySize, SM128);
    cudaFuncSetAttribute(gemm_nt<128, 1, 0, 0, 0>,
                         cudaFuncAttributeMaxDynamicSharedMemorySize, SM128);
    cudaFuncSetAttribute(gemm_nt<128, 0, 1, 1, 0>,
                         cudaFuncAttributeMaxDynamicSharedMemorySize, SM128);

    dim3 blk(256);

    // prep: x split + weight transpose/split
    xsplit_kernel<<<MROWS * CDIM / 4 / 256, blk>>>(x, xh, xl);
    wprep_kernel<<<576, blk>>>(Wf, Wg, Wh, Wv,
                               fgth, fgtl, whth, whtl, wvth, wvtl);

    // fg proj: f,g split bf16 (K padded to 64).  M=16384, N=64, K=256
    gemm_nt<64, 1, 0, 0, 2><<<dim3(MROWS / 128, 1, 1), blk, SM64>>>(
        xh, xl, 0, fgth, fgtl, 0,
        fh, fl, gh, gl, 0, KPAD, bf, bg, nullptr, CDIM);

    // hm^T proj: hm^T split bf16, bias on rows.  M=256, N=16384, K=256
    gemm_nt<128, 1, 2, 0, 1><<<dim3(CDIM / 128, MROWS / 128, 1), blk, SM128>>>(
        whth, whtl, 0, xh, xl, 0,
        th, tl, nullptr, nullptr, 0, 0, bh, nullptr, nullptr, CDIM);

    // s = g @ f^T (fp32), per batch.  M=N=4096, K=64(padded)
    gemm_nt<128, 0, 0, 0, 0><<<dim3(NPIX / 128, NPIX / 128, BATCH), blk, SM128>>>(
        gh, gl, (long long)NPIX * KPAD, fh, fl, (long long)NPIX * KPAD,
        ps, nullptr, nullptr, nullptr,
        (long long)NPIX * NPIX, NPIX, nullptr, nullptr, nullptr, KPAD);

    // beta = softmax(s) -> split bf16
    softmax_kernel<<<dim3(BATCH * NPIX), blk>>>(ps, bbh, bbl);

    // o = beta @ hm (split bf16 out), per batch.  M=4096, N=256, K=4096
    gemm_nt<128, 1, 0, 0, 0><<<dim3(NPIX / 128, CDIM / 128, BATCH), blk, SM128>>>(
        bbh, bbl, (long long)NPIX * NPIX, th, tl, (long long)CDIM * NPIX,
        oh, ol, nullptr, nullptr,
        (long long)NPIX * CDIM, CDIM, nullptr, nullptr, nullptr, NPIX);

    // out = x + o @ Wv + bv (fp32).  M=16384, N=256, K=256
    gemm_nt<128, 0, 1, 1, 0><<<dim3(MROWS / 128, CDIM / 128, 1), blk, SM128>>>(
        oh, ol, 0, wvth, wvtl, 0,
        out, nullptr, nullptr, nullptr, 0, CDIM, bv, nullptr, x, CDIM);
}

// round 11
// speedup vs baseline: 3.0563x; 1.4184x over previous
#include <cuda_runtime.h>
#include <cuda_bf16.h>
#include <cstdint>

// ---------------------------------------------------------------------------
// SelfAttention (SAGAN-style), B=4, N=4096, C=256, Ck=32.
// mma.sync.m16n8k16 bf16 split everywhere (fp32 acc); attention core is now a
// two-pass flash fusion:
//   pass A: row-max of s = g f^T (no exp, nothing stored but m[row])
//   pass B: recompute s chunk-wise, p = exp2((s-m)log2e) (once per score),
//           o_unnorm += p @ hm (p split hi/lo via smem; hm single bf16-hi),
//           row-sum accumulated alongside; divide in epilogue -> o split bf16.
// This removes the 256MB fp32 score tensor and all beta traffic (~1.5 GB).
// ---------------------------------------------------------------------------

#define BATCH 4
#define NPIX  4096
#define CDIM  256
#define CKDIM 32
#define MROWS 16384
#define KPAD  64

typedef __nv_bfloat16 bf16;

// Scratch (static __device__, 16B-aligned)
static __device__ __align__(16) bf16 g_xh[MROWS * CDIM];
static __device__ __align__(16) bf16 g_xl[MROWS * CDIM];
static __device__ __align__(16) bf16 g_wfgt_h[64 * CDIM];
static __device__ __align__(16) bf16 g_wfgt_l[64 * CDIM];
static __device__ __align__(16) bf16 g_wht_h[CDIM * CDIM];
static __device__ __align__(16) bf16 g_wht_l[CDIM * CDIM];
static __device__ __align__(16) bf16 g_wvt_h[CDIM * CDIM];
static __device__ __align__(16) bf16 g_wvt_l[CDIM * CDIM];
static __device__ __align__(16) bf16 g_fh[MROWS * KPAD];
static __device__ __align__(16) bf16 g_fl[MROWS * KPAD];
static __device__ __align__(16) bf16 g_gh[MROWS * KPAD];
static __device__ __align__(16) bf16 g_gl[MROWS * KPAD];
static __device__ __align__(16) bf16 g_th[(size_t)BATCH * CDIM * NPIX];
static __device__ __align__(16) bf16 g_tl[(size_t)BATCH * CDIM * NPIX];
static __device__ __align__(16) float g_m[MROWS];                 // row maxes
static __device__ __align__(16) bf16 g_oh[MROWS * CDIM];
static __device__ __align__(16) bf16 g_ol[MROWS * CDIM];

// --- PTX helpers ------------------------------------------------------------
__device__ __forceinline__ uint32_t smem_u32(const void* p) {
    uint32_t a;
    asm("{ .reg .u64 t; cvta.to.shared.u64 t, %1; cvt.u32.u64 %0, t; }"
        : "=r"(a) : "l"(p));
    return a;
}

#define SWZ128(off) ((off) ^ (((off) >> 3) & 0x70u))

#define LDSM4(r, addr) \
    asm volatile("ldmatrix.sync.aligned.m8n8.x4.shared.b16 {%0,%1,%2,%3}, [%4];" \
        : "=r"((r)[0]), "=r"((r)[1]), "=r"((r)[2]), "=r"((r)[3]) : "r"(addr))

#define MMA16816(d, a, b0, b1) \
    asm volatile("mma.sync.aligned.m16n8k16.row.col.f32.bf16.bf16.f32 " \
        "{%0,%1,%2,%3}, {%4,%5,%6,%7}, {%8,%9}, {%0,%1,%2,%3};" \
        : "+f"((d)[0]), "+f"((d)[1]), "+f"((d)[2]), "+f"((d)[3]) \
        : "r"((a)[0]), "r"((a)[1]), "r"((a)[2]), "r"((a)[3]), "r"(b0), "r"(b1))

#define CP16(smaddr, gptr) \
    asm volatile("cp.async.cg.shared.global [%0], [%1], 16;" \
        :: "r"(smaddr), "l"(gptr))
#define CP_COMMIT() asm volatile("cp.async.commit_group;" ::: "memory")
#define CP_WAIT1()  asm volatile("cp.async.wait_group 1;" ::: "memory")
#define CP_WAIT0()  asm volatile("cp.async.wait_group 0;" ::: "memory")

#define STS32(addr, v) \
    asm volatile("st.shared.b32 [%0], %1;" :: "r"(addr), "r"(v))

__device__ __forceinline__ float ex2f(float x) {
    float r; asm("ex2.approx.f32 %0, %1;" : "=f"(r) : "f"(x)); return r;
}
__device__ __forceinline__ uint32_t pack_hi(float a, float b) {
    __nv_bfloat162 h; h.x = __float2bfloat16(a); h.y = __float2bfloat16(b);
    return *(uint32_t*)&h;
}
__device__ __forceinline__ uint32_t pack_lo(float a, float b) {
    bf16 ha = __float2bfloat16(a), hb = __float2bfloat16(b);
    __nv_bfloat162 l;
    l.x = __float2bfloat16(a - __bfloat162float(ha));
    l.y = __float2bfloat16(b - __bfloat162float(hb));
    return *(uint32_t*)&l;
}

// ---------------------------------------------------------------------------
// x -> split bf16 (hi/lo)
// ---------------------------------------------------------------------------
__global__ __launch_bounds__(256)
void xsplit_kernel(const float* __restrict__ X,
                   bf16* __restrict__ H, bf16* __restrict__ L)
{
    int i = blockIdx.x * 256 + threadIdx.x;
    float4 v = reinterpret_cast<const float4*>(X)[i];
    reinterpret_cast<uint32_t*>(H + (size_t)i * 4)[0] = pack_hi(v.x, v.y);
    reinterpret_cast<uint32_t*>(H + (size_t)i * 4)[1] = pack_hi(v.z, v.w);
    reinterpret_cast<uint32_t*>(L + (size_t)i * 4)[0] = pack_lo(v.x, v.y);
    reinterpret_cast<uint32_t*>(L + (size_t)i * 4)[1] = pack_lo(v.z, v.w);
}

// ---------------------------------------------------------------------------
// Weight prep: transpose + split.
// ---------------------------------------------------------------------------
__global__ __launch_bounds__(256)
void wprep_kernel(const float* __restrict__ Wf, const float* __restrict__ Wg,
                  const float* __restrict__ Wh, const float* __restrict__ Wv,
                  bf16* __restrict__ FGh, bf16* __restrict__ FGl,
                  bf16* __restrict__ WHh, bf16* __restrict__ WHl,
                  bf16* __restrict__ WVh, bf16* __restrict__ WVl)
{
    int r = blockIdx.x;
    int k = threadIdx.x;
    float w;
    bf16 *ph, *pl;
    int out;
    if (r < 64) {
        w = (r < 32) ? Wf[k * CKDIM + r] : Wg[k * CKDIM + (r - 32)];
        ph = FGh; pl = FGl; out = r * CDIM + k;
    } else if (r < 320) {
        int c = r - 64;
        w = Wh[k * CDIM + c];
        ph = WHh; pl = WHl; out = c * CDIM + k;
    } else {
        int c = r - 320;
        w = Wv[k * CDIM + c];
        ph = WVh; pl = WVl; out = c * CDIM + k;
    }
    bf16 h = __float2bfloat16(w);
    ph[out] = h;
    pl[out] = __float2bfloat16(w - __bfloat162float(h));
}

// ---------------------------------------------------------------------------
// Generic NT GEMM (unchanged, proven in R9)
// ---------------------------------------------------------------------------
template<int NT, int OUT, int BIAS, int RES, int NMAP>
__global__ void __launch_bounds__(256, 1)
gemm_nt(const bf16* __restrict__ Ah, const bf16* __restrict__ Al, long long sA,
        const bf16* __restrict__ Bh, const bf16* __restrict__ Bl, long long sB,
        void* __restrict__ C0, void* __restrict__ C1,
        void* __restrict__ C2, void* __restrict__ C3,
        long long sC, int ldC,
        const float* __restrict__ bias, const float* __restrict__ bias2,
        const float* __restrict__ resid, int K)
{
    extern __shared__ __align__(1024) char gsm[];
    constexpr int AHo = 0;
    constexpr int ALo = 128 * 128;
    constexpr int BHo = 2 * 128 * 128;
    constexpr int BLo = BHo + NT * 128;
    constexpr int STG = BHo + 2 * NT * 128;

    const int t    = threadIdx.x;
    const int lane = t & 31;
    const int wid  = t >> 5;
    const int wm   = wid >> 1;
    const int wn   = wid & 1;
    const int m0   = blockIdx.x * 128;
    const int n0   = blockIdx.y * NT;
    const int z    = blockIdx.z;

    const uint32_t smb = smem_u32(gsm);
    const bf16* pAh = Ah + (size_t)z * sA + (size_t)m0 * K;
    const bf16* pAl = Al + (size_t)z * sA + (size_t)m0 * K;
    const bf16* pBh = Bh + (size_t)z * sB + (size_t)n0 * K;
    const bf16* pBl = Bl + (size_t)z * sB + (size_t)n0 * K;

    float acc[2][NT / 16][4];
    #pragma unroll
    for (int mt = 0; mt < 2; mt++)
      #pragma unroll
      for (int nt = 0; nt < NT / 16; nt++)
        #pragma unroll
        for (int q = 0; q < 4; q++)
            acc[mt][nt][q] = 0.f;

    auto load_stage = [&](int s, int c) {
        const uint32_t sb = smb + s * STG;
        const int k0 = c * 64;
        #pragma unroll
        for (int i = 0; i < 4; i++) {
            int idx = t + 256 * i;
            int row = idx >> 3, col = idx & 7;
            uint32_t off = SWZ128((uint32_t)(row * 128 + col * 16));
            CP16(sb + AHo + off, (const char*)(pAh + (size_t)row * K + k0) + col * 16);
            CP16(sb + ALo + off, (const char*)(pAl + (size_t)row * K + k0) + col * 16);
        }
        #pragma unroll
        for (int i = 0; i < NT / 32; i++) {
            int idx = t + 256 * i;
            int row = idx >> 3, col = idx & 7;
            uint32_t off = SWZ128((uint32_t)(row * 128 + col * 16));
            CP16(sb + BHo + off, (const char*)(pBh + (size_t)row * K + k0) + col * 16);
            CP16(sb + BLo + off, (const char*)(pBl + (size_t)row * K + k0) + col * 16);
        }
    };

    const int chunks = K >> 6;
    load_stage(0, 0);
    CP_COMMIT();

    for (int c = 0; c < chunks; ++c) {
        if (c + 1 < chunks) {
            load_stage((c + 1) & 1, c + 1);
            CP_COMMIT();
            CP_WAIT1();
        } else {
            CP_WAIT0();
        }
        __syncthreads();

        const uint32_t sb  = smb + (c & 1) * STG;
        const uint32_t sAh = sb + AHo, sAl = sb + ALo;
        const uint32_t sBh = sb + BHo, sBl = sb + BLo;

        #pragma unroll
        for (int ks = 0; ks < 4; ks++) {
            const uint32_t kbyte = ks * 32 + ((lane >> 4) << 4);

            uint32_t afh[2][4], afl[2][4];
            #pragma unroll
            for (int mt = 0; mt < 2; mt++) {
                int row = wm * 32 + mt * 16 + (lane & 15);
                uint32_t off = SWZ128((uint32_t)(row * 128) + kbyte);
                LDSM4(afh[mt], sAh + off);
                LDSM4(afl[mt], sAl + off);
            }

            #pragma unroll
            for (int ntp = 0; ntp < NT / 32; ntp++) {
                int row = wn * (NT / 2) + ntp * 16 + (lane & 15);
                uint32_t off = SWZ128((uint32_t)(row * 128) + kbyte);
                uint32_t bfh[4], bfl[4];
                LDSM4(bfh, sBh + off);
                LDSM4(bfl, sBl + off);
                #pragma unroll
                for (int h = 0; h < 2; h++) {
                    uint32_t b0h = h ? bfh[1] : bfh[0];
                    uint32_t b1h = h ? bfh[3] : bfh[2];
                    uint32_t b0l = h ? bfl[1] : bfl[0];
                    uint32_t b1l = h ? bfl[3] : bfl[2];
                    const int nt = ntp * 2 + h;
                    #pragma unroll
                    for (int mt = 0; mt < 2; mt++) {
                        MMA16816(acc[mt][nt], afh[mt], b0h, b1h);
                        MMA16816(acc[mt][nt], afh[mt], b0l, b1l);
                        MMA16816(acc[mt][nt], afl[mt], b0h, b1h);
                    }
                }
            }
        }
        __syncthreads();
    }

    const int g = lane >> 2;
    const int q = lane & 3;

    auto store2 = [&](int rg, int cg, float v0, float v1) {
        if constexpr (BIAS == 1) { v0 += bias[cg]; v1 += bias[cg + 1]; }
        if constexpr (BIAS == 2) { float bb = bias[rg]; v0 += bb; v1 += bb; }

        if constexpr (NMAP == 2) {
            bool isf = (cg < 32);
            float b0 = isf ? bias[cg]  : bias2[cg - 32];
            float b1 = isf ? bias[cg + 1] : bias2[cg - 31];
            v0 += b0; v1 += b1;
            uint32_t hp = pack_hi(v0, v1);
            uint32_t lp = pack_lo(v0, v1);
            uint32_t zp = pack_hi(0.f, 0.f);
            size_t rowb = (size_t)rg * KPAD;
            if (isf) {
                *(uint32_t*)((bf16*)C0 + rowb + cg) = hp;
                *(uint32_t*)((bf16*)C1 + rowb + cg) = lp;
                *(uint32_t*)((bf16*)C0 + rowb + cg + 32) = zp;
                *(uint32_t*)((bf16*)C1 + rowb + cg + 32) = zp;
            } else {
                *(uint32_t*)((bf16*)C2 + rowb + cg - 32) = hp;
                *(uint32_t*)((bf16*)C3 + rowb + cg - 32) = lp;
                *(uint32_t*)((bf16*)C2 + rowb + cg) = zp;
                *(uint32_t*)((bf16*)C3 + rowb + cg) = zp;
            }
        } else if constexpr (OUT == 0) {
            size_t off = (size_t)z * sC + (size_t)rg * ldC + cg;
            if constexpr (RES) {
                v0 += resid[(size_t)rg * ldC + cg];
                v1 += resid[(size_t)rg * ldC + cg + 1];
            }
            *(float2*)((float*)C0 + off) = make_float2(v0, v1);
        } else {
            size_t off;
            if constexpr (NMAP == 1) {
                int bb = cg >> 12, nn = cg & 4095;
                off = ((size_t)(bb * CDIM + rg)) * NPIX + nn;
            } else {
                off = (size_t)z * sC + (size_t)rg * ldC + cg;
            }
            *(uint32_t*)((bf16*)C0 + off) = pack_hi(v0, v1);
            *(uint32_t*)((bf16*)C1 + off) = pack_lo(v0, v1);
        }
    };

    #pragma unroll
    for (int mt = 0; mt < 2; mt++) {
        #pragma unroll
        for (int nt = 0; nt < NT / 16; nt++) {
            int rg = m0 + wm * 32 + mt * 16 + g;
            int cg = n0 + wn * (NT / 2) + nt * 8 + q * 2;
            store2(rg,     cg, acc[mt][nt][0], acc[mt][nt][1]);
            store2(rg + 8, cg, acc[mt][nt][2], acc[mt][nt][3]);
        }
    }
}

// ---------------------------------------------------------------------------
// Pass A: per-row max of s = g @ f^T (3-term split, K=32 real).
// grid (32,1,4), 256 threads (8 warps, 16 rows each). Key chunks of 128.
// ---------------------------------------------------------------------------
#define RA_G_HI 0
#define RA_G_LO 16384
#define RA_ST(s) (32768 + (s) * 32768)    // f_hi +0 (16K), f_lo +16K
#define RA_SMEM  98304

__global__ void __launch_bounds__(256, 1)
rowmax_kernel(const bf16* __restrict__ gh, const bf16* __restrict__ gl,
              const bf16* __restrict__ fh, const bf16* __restrict__ fl,
              float* __restrict__ M)
{
    extern __shared__ __align__(1024) char rsm[];
    const int t = threadIdx.x, lane = t & 31, w = t >> 5;
    const int b = blockIdx.z, m0 = blockIdx.x * 128;
    const uint32_t smb = smem_u32(rsm);
    const uint32_t kb = (uint32_t)((lane >> 4) << 4);

    {
        const char* sH = (const char*)(gh + (size_t)(b * NPIX + m0) * KPAD);
        const char* sL = (const char*)(gl + (size_t)(b * NPIX + m0) * KPAD);
        #pragma unroll
        for (int i = 0; i < 4; i++) {
            int idx = t + 256 * i;
            int row = idx >> 3, col = idx & 7;
            uint32_t off = SWZ128((uint32_t)(row * 128 + col * 16));
            CP16(smb + RA_G_HI + off, sH + (size_t)row * 128 + col * 16);
            CP16(smb + RA_G_LO + off, sL + (size_t)row * 128 + col * 16);
        }
    }
    auto loadf = [&](int s, int c) {
        const int k0 = c * 128;
        const char* sH = (const char*)(fh + (size_t)(b * NPIX + k0) * KPAD);
        const char* sL = (const char*)(fl + (size_t)(b * NPIX + k0) * KPAD);
        #pragma unroll
        for (int i = 0; i < 4; i++) {
            int idx = t + 256 * i;
            int row = idx >> 3, col = idx & 7;
            uint32_t off = SWZ128((uint32_t)(row * 128 + col * 16));
            CP16(smb + RA_ST(s) + off,         sH + (size_t)row * 128 + col * 16);
            CP16(smb + RA_ST(s) + 16384 + off, sL + (size_t)row * 128 + col * 16);
        }
    };
    loadf(0, 0);
    CP_COMMIT();

    float mx0 = -3.4e38f, mx1 = -3.4e38f;

    for (int c = 0; c < 32; c++) {
        if (c + 1 < 32) { loadf((c + 1) & 1, c + 1); CP_COMMIT(); CP_WAIT1(); }
        else            { CP_WAIT0(); }
        __syncthreads();

        const uint32_t gH = smb + RA_G_HI, gL = smb + RA_G_LO;
        const uint32_t fH = smb + RA_ST(c & 1), fL = fH + 16384;

        uint32_t ah[2][4], al[2][4];
        #pragma unroll
        for (int ks = 0; ks < 2; ks++) {
            uint32_t off = SWZ128((uint32_t)((16 * w + (lane & 15)) * 128) + ks * 32 + kb);
            LDSM4(ah[ks], gH + off);
            LDSM4(al[ks], gL + off);
        }
        #pragma unroll
        for (int ntp = 0; ntp < 8; ntp++) {
            float fr[2][4] = {{0.f,0.f,0.f,0.f},{0.f,0.f,0.f,0.f}};
            #pragma unroll
            for (int ks = 0; ks < 2; ks++) {
                uint32_t off = SWZ128((uint32_t)((ntp * 16 + (lane & 15)) * 128) + ks * 32 + kb);
                uint32_t bh[4], bl[4];
                LDSM4(bh, fH + off);
                LDSM4(bl, fL + off);
                #pragma unroll
                for (int h = 0; h < 2; h++) {
                    uint32_t b0h = h ? bh[1] : bh[0], b1h = h ? bh[3] : bh[2];
                    uint32_t b0l = h ? bl[1] : bl[0], b1l = h ? bl[3] : bl[2];
                    MMA16816(fr[h], ah[ks], b0h, b1h);
                    MMA16816(fr[h], ah[ks], b0l, b1l);
                    MMA16816(fr[h], al[ks], b0h, b1h);
                }
            }
            #pragma unroll
            for (int h = 0; h < 2; h++) {
                mx0 = fmaxf(mx0, fmaxf(fr[h][0], fr[h][1]));
                mx1 = fmaxf(mx1, fmaxf(fr[h][2], fr[h][3]));
            }
        }
        __syncthreads();
    }

    mx0 = fmaxf(mx0, __shfl_xor_sync(~0u, mx0, 1));
    mx0 = fmaxf(mx0, __shfl_xor_sync(~0u, mx0, 2));
    mx1 = fmaxf(mx1, __shfl_xor_sync(~0u, mx1, 1));
    mx1 = fmaxf(mx1, __shfl_xor_sync(~0u, mx1, 2));
    if ((lane & 3) == 0) {
        int r = m0 + 16 * w + (lane >> 2);
        M[(size_t)b * NPIX + r]     = mx0;
        M[(size_t)b * NPIX + r + 8] = mx1;
    }
}

// ---------------------------------------------------------------------------
// Pass B: fused s -> exp -> o (unnormalized) -> normalize.
// grid (32,1,4), 512 threads (16 warps: wm=w>>1 rows 16wm, wn=w&1).
// Key chunks of 64. p stored split-bf16 in smem (double-buffered).
// o uses 2 terms: p_hi*hm_hi + p_lo*hm_hi (hm lo dropped, error ~1e-5 final).
// ---------------------------------------------------------------------------
#define FB_G_HI 0
#define FB_G_LO 16384
#define FB_ST(s) (32768 + (s) * 49152)   // f_hi +0 (8K), f_lo +8K, hm +16K (32K)
#define FB_P(s)  (131072 + (s) * 32768)  // p_hi +0 (16K), p_lo +16K
#define FB_SMEM  196608

__global__ void __launch_bounds__(512, 1)
fused_attn_kernel(const bf16* __restrict__ gh, const bf16* __restrict__ gl,
                  const bf16* __restrict__ fh, const bf16* __restrict__ fl,
                  const bf16* __restrict__ hmT,
                  const float* __restrict__ M,
                  bf16* __restrict__ oh, bf16* __restrict__ ol)
{
    extern __shared__ __align__(1024) char fsm[];
    __shared__ float rsum[2][128];
    const int t = threadIdx.x, lane = t & 31, w = t >> 5;
    const int wm = w >> 1, wn = w & 1;
    const int b = blockIdx.z, m0 = blockIdx.x * 128;
    const int g = lane >> 2, q = lane & 3;
    const uint32_t smb = smem_u32(fsm);
    const uint32_t kb = (uint32_t)((lane >> 4) << 4);
    const float l2e = 1.4426950408889634f;

    const float mc0 = M[(size_t)b * NPIX + m0 + 16 * wm + g] * l2e;
    const float mc1 = M[(size_t)b * NPIX + m0 + 16 * wm + 8 + g] * l2e;

    // g tile: 1024 16B-units per array, 2/thread
    {
        const char* sH = (const char*)(gh + (size_t)(b * NPIX + m0) * KPAD);
        const char* sL = (const char*)(gl + (size_t)(b * NPIX + m0) * KPAD);
        #pragma unroll
        for (int i = 0; i < 2; i++) {
            int idx = t + 512 * i;
            int row = idx >> 3, col = idx & 7;
            uint32_t off = SWZ128((uint32_t)(row * 128 + col * 16));
            CP16(smb + FB_G_HI + off, sH + (size_t)row * 128 + col * 16);
            CP16(smb + FB_G_LO + off, sL + (size_t)row * 128 + col * 16);
        }
    }
    auto loadc = [&](int s, int c) {
        const int k0 = c * 64;
        {   // f: 64 rows x 8 units = 512, 1/thread per array
            int row = t >> 3, col = t & 7;
            uint32_t off = SWZ128((uint32_t)(row * 128 + col * 16));
            CP16(smb + FB_ST(s) + off,
                 (const char*)(fh + (size_t)(b * NPIX + k0 + row) * KPAD) + col * 16);
            CP16(smb + FB_ST(s) + 8192 + off,
                 (const char*)(fl + (size_t)(b * NPIX + k0 + row) * KPAD) + col * 16);
        }
        #pragma unroll
        for (int i = 0; i < 4; i++) {   // hm: 256 rows x 8 units = 2048
            int idx = t + 512 * i;
            int row = idx >> 3, col = idx & 7;
            uint32_t off = SWZ128((uint32_t)(row * 128 + col * 16));
            CP16(smb + FB_ST(s) + 16384 + off,
                 (const char*)(hmT + ((size_t)(b * CDIM + row) * NPIX + k0)) + col * 16);
        }
    };
    loadc(0, 0);
    CP_COMMIT();

    float acc[16][4];
    #pragma unroll
    for (int nt = 0; nt < 16; nt++)
        #pragma unroll
        for (int i = 0; i < 4; i++) acc[nt][i] = 0.f;
    float sum0 = 0.f, sum1 = 0.f;

    for (int c = 0; c < 64; c++) {
        CP_WAIT0();
        __syncthreads();                       // chunk c data + all past phases

        const uint32_t gH = smb + FB_G_HI, gL = smb + FB_G_LO;
        const uint32_t stb = smb + FB_ST(c & 1);
        const uint32_t fH = stb, fL = stb + 8192, hmS = stb + 16384;
        const uint32_t pH = smb + FB_P(c & 1), pL = pH + 16384;

        // ---- s-phase: rows 16wm x keys [32wn, 32wn+32) ----
        {
            uint32_t ah[2][4], al[2][4];
            #pragma unroll
            for (int ks = 0; ks < 2; ks++) {
                uint32_t off = SWZ128((uint32_t)((16 * wm + (lane & 15)) * 128) + ks * 32 + kb);
                LDSM4(ah[ks], gH + off);
                LDSM4(al[ks], gL + off);
            }
            #pragma unroll
            for (int ntp = 0; ntp < 2; ntp++) {
                float fr[2][4] = {{0.f,0.f,0.f,0.f},{0.f,0.f,0.f,0.f}};
                #pragma unroll
                for (int ks = 0; ks < 2; ks++) {
                    uint32_t off = SWZ128((uint32_t)((32 * wn + ntp * 16 + (lane & 15)) * 128)
                                          + ks * 32 + kb);
                    uint32_t bh[4], bl[4];
                    LDSM4(bh, fH + off);
                    LDSM4(bl, fL + off);
                    #pragma unroll
                    for (int h = 0; h < 2; h++) {
                        uint32_t b0h = h ? bh[1] : bh[0], b1h = h ? bh[3] : bh[2];
                        uint32_t b0l = h ? bl[1] : bl[0], b1l = h ? bl[3] : bl[2];
                        MMA16816(fr[h], ah[ks], b0h, b1h);
                        MMA16816(fr[h], ah[ks], b0l, b1l);
                        MMA16816(fr[h], al[ks], b0h, b1h);
                    }
                }
                #pragma unroll
                for (int h = 0; h < 2; h++) {
                    int key = 32 * wn + ntp * 16 + h * 8 + 2 * q;
                    float p0 = ex2f(fmaf(fr[h][0], l2e, -mc0));
                    float p1 = ex2f(fmaf(fr[h][1], l2e, -mc0));
                    float p2 = ex2f(fmaf(fr[h][2], l2e, -mc1));
                    float p3 = ex2f(fmaf(fr[h][3], l2e, -mc1));
                    sum0 += p0 + p1;
                    sum1 += p2 + p3;
                    uint32_t a0 = SWZ128((uint32_t)((16 * wm + g) * 128 + key * 2));
                    uint32_t a1 = SWZ128((uint32_t)((16 * wm + 8 + g) * 128 + key * 2));
                    STS32(pH + a0, pack_hi(p0, p1));
                    STS32(pL + a0, pack_lo(p0, p1));
                    STS32(pH + a1, pack_hi(p2, p3));
                    STS32(pL + a1, pack_lo(p2, p3));
                }
            }
        }
        __syncthreads();                       // p complete; everyone past o(c-1)

        if (c + 1 < 64) { loadc((c + 1) & 1, c + 1); CP_COMMIT(); }

        // ---- o-phase: rows 16wm x channels [128wn, 128wn+128), 2-term ----
        #pragma unroll
        for (int ks = 0; ks < 4; ks++) {
            uint32_t offA = SWZ128((uint32_t)((16 * wm + (lane & 15)) * 128) + ks * 32 + kb);
            uint32_t aph[4], apl[4];
            LDSM4(aph, pH + offA);
            LDSM4(apl, pL + offA);
            #pragma unroll
            for (int ntp = 0; ntp < 8; ntp++) {
                uint32_t off = SWZ128((uint32_t)((128 * wn + ntp * 16 + (lane & 15)) * 128)
                                      + ks * 32 + kb);
                uint32_t bh[4];
                LDSM4(bh, hmS + off);
                #pragma unroll
                for (int h = 0; h < 2; h++) {
                    uint32_t b0 = h ? bh[1] : bh[0], b1 = h ? bh[3] : bh[2];
                    MMA16816(acc[ntp * 2 + h], aph, b0, b1);
                    MMA16816(acc[ntp * 2 + h], apl, b0, b1);
                }
            }
        }
    }

    // ---- normalize + store o split-bf16 ----
    sum0 += __shfl_xor_sync(~0u, sum0, 1);
    sum0 += __shfl_xor_sync(~0u, sum0, 2);
    sum1 += __shfl_xor_sync(~0u, sum1, 1);
    sum1 += __shfl_xor_sync(~0u, sum1, 2);
    if ((lane & 3) == 0) {
        rsum[wn][16 * wm + g] = sum0;
        rsum[wn][16 * wm + 8 + g] = sum1;
    }
    __syncthreads();
    const float inv0 = 1.f / (rsum[0][16 * wm + g]     + rsum[1][16 * wm + g]);
    const float inv1 = 1.f / (rsum[0][16 * wm + 8 + g] + rsum[1][16 * wm + 8 + g]);

    #pragma unroll
    for (int nt = 0; nt < 16; nt++) {
        int ch = 128 * wn + nt * 8 + 2 * q;
        float v0 = acc[nt][0] * inv0, v1 = acc[nt][1] * inv0;
        float v2 = acc[nt][2] * inv1, v3 = acc[nt][3] * inv1;
        size_t o0 = ((size_t)(b * NPIX + m0 + 16 * wm + g)) * CDIM + ch;
        size_t o1 = ((size_t)(b * NPIX + m0 + 16 * wm + 8 + g)) * CDIM + ch;
        *(uint32_t*)(oh + o0) = pack_hi(v0, v1);
        *(uint32_t*)(ol + o0) = pack_lo(v0, v1);
        *(uint32_t*)(oh + o1) = pack_hi(v2, v3);
        *(uint32_t*)(ol + o1) = pack_lo(v2, v3);
    }
}

// ---------------------------------------------------------------------------
extern "C" void kernel_launch(void* const* d_in, const int* in_sizes, int n_in,
                              void* d_out, int out_size)
{
    (void)in_sizes; (void)n_in; (void)out_size;
    const float* x  = (const float*)d_in[0];
    const float* Wf = (const float*)d_in[1];
    const float* bf = (const float*)d_in[2];
    const float* Wg = (const float*)d_in[3];
    const float* bg = (const float*)d_in[4];
    const float* Wh = (const float*)d_in[5];
    const float* bh = (const float*)d_in[6];
    const float* Wv = (const float*)d_in[7];
    const float* bv = (const float*)d_in[8];
    float* out = (float*)d_out;

    bf16 *xh, *xl, *fgth, *fgtl, *whth, *whtl, *wvth, *wvtl;
    bf16 *fh, *fl, *gh, *gl, *th, *tl, *oh, *ol;
    float* pm;
    cudaGetSymbolAddress((void**)&xh,   g_xh);
    cudaGetSymbolAddress((void**)&xl,   g_xl);
    cudaGetSymbolAddress((void**)&fgth, g_wfgt_h);
    cudaGetSymbolAddress((void**)&fgtl, g_wfgt_l);
    cudaGetSymbolAddress((void**)&whth, g_wht_h);
    cudaGetSymbolAddress((void**)&whtl, g_wht_l);
    cudaGetSymbolAddress((void**)&wvth, g_wvt_h);
    cudaGetSymbolAddress((void**)&wvtl, g_wvt_l);
    cudaGetSymbolAddress((void**)&fh,   g_fh);
    cudaGetSymbolAddress((void**)&fl,   g_fl);
    cudaGetSymbolAddress((void**)&gh,   g_gh);
    cudaGetSymbolAddress((void**)&gl,   g_gl);
    cudaGetSymbolAddress((void**)&th,   g_th);
    cudaGetSymbolAddress((void**)&tl,   g_tl);
    cudaGetSymbolAddress((void**)&pm,   g_m);
    cudaGetSymbolAddress((void**)&oh,   g_oh);
    cudaGetSymbolAddress((void**)&ol,   g_ol);

    const int SM128 = 2 * (2 * 128 * 128 + 2 * 128 * 128);
    const int SM64  = 2 * (2 * 128 * 128 + 2 * 64 * 128);
    cudaFuncSetAttribute(gemm_nt<64, 1, 0, 0, 2>,
                         cudaFuncAttributeMaxDynamicSharedMemorySize, SM64);
    cudaFuncSetAttribute(gemm_nt<128, 1, 2, 0, 1>,
                         cudaFuncAttributeMaxDynamicSharedMemorySize, SM128);
    cudaFuncSetAttribute(gemm_nt<128, 0, 1, 1, 0>,
                         cudaFuncAttributeMaxDynamicSharedMemorySize, SM128);
    cudaFuncSetAttribute(rowmax_kernel,
                         cudaFuncAttributeMaxDynamicSharedMemorySize, RA_SMEM);
    cudaFuncSetAttribute(fused_attn_kernel,
                         cudaFuncAttributeMaxDynamicSharedMemorySize, FB_SMEM);

    dim3 blk(256);

    // prep: x split + weight transpose/split
    xsplit_kernel<<<MROWS * CDIM / 4 / 256, blk>>>(x, xh, xl);
    wprep_kernel<<<576, blk>>>(Wf, Wg, Wh, Wv,
                               fgth, fgtl, whth, whtl, wvth, wvtl);

    // fg proj: f,g split bf16 (K padded to 64)
    gemm_nt<64, 1, 0, 0, 2><<<dim3(MROWS / 128, 1, 1), blk, SM64>>>(
        xh, xl, 0, fgth, fgtl, 0,
        fh, fl, gh, gl, 0, KPAD, bf, bg, nullptr, CDIM);

    // hm^T proj: split bf16, bias on rows (lo written but unused downstream hi-only ok; kept for v-proj? no — th only)
    gemm_nt<128, 1, 2, 0, 1><<<dim3(CDIM / 128, MROWS / 128, 1), blk, SM128>>>(
        whth, whtl, 0, xh, xl, 0,
        th, tl, nullptr, nullptr, 0, 0, bh, nullptr, nullptr, CDIM);

    // pass A: row maxes of s
    rowmax_kernel<<<dim3(NPIX / 128, 1, BATCH), blk, RA_SMEM>>>(
        gh, gl, fh, fl, pm);

    // pass B: fused exp + o (unnormalized) + normalize -> o split bf16
    fused_attn_kernel<<<dim3(NPIX / 128, 1, BATCH), dim3(512), FB_SMEM>>>(
        gh, gl, fh, fl, th, pm, oh, ol);

    // out = x + o @ Wv + bv (fp32)
    gemm_nt<128, 0, 1, 1, 0><<<dim3(MROWS / 128, CDIM / 128, 1), blk, SM128>>>(
        oh, ol, 0, wvth, wvtl, 0,
        out, nullptr, nullptr, nullptr, 0, CDIM, bv, nullptr, x, CDIM);
}

// round 12
// speedup vs baseline: 4.2993x; 1.4067x over previous
#include <cuda_runtime.h>
#include <cuda_bf16.h>
#include <cuda_fp16.h>
#include <cstdint>

// ---------------------------------------------------------------------------
// SelfAttention (SAGAN-style), B=4, N=4096, C=256, Ck=32.
// Projections / v-proj: bf16 split 3-term mma.sync (proven R9 path).
// Attention core now fp16:
//   pass A (rowmax): 1-term fp16 (m error is per-row constant -> cancels)
//   pass B (fused): s = 3-term fp16 split; p = exp(s - m_row) in fp16 (hi only);
//                   o += p @ hm with hm single fp16 -> 1 MMA term.
// ---------------------------------------------------------------------------

#define BATCH 4
#define NPIX  4096
#define CDIM  256
#define CKDIM 32
#define MROWS 16384
#define KPAD  64

typedef __nv_bfloat16 bf16;

// Scratch (static __device__, 16B-aligned)
static __device__ __align__(16) bf16   g_xh[MROWS * CDIM];
static __device__ __align__(16) bf16   g_xl[MROWS * CDIM];
static __device__ __align__(16) bf16   g_wfgt_h[64 * CDIM];
static __device__ __align__(16) bf16   g_wfgt_l[64 * CDIM];
static __device__ __align__(16) bf16   g_wht_h[CDIM * CDIM];
static __device__ __align__(16) bf16   g_wht_l[CDIM * CDIM];
static __device__ __align__(16) bf16   g_wvt_h[CDIM * CDIM];
static __device__ __align__(16) bf16   g_wvt_l[CDIM * CDIM];
static __device__ __align__(16) __half g_fh[MROWS * KPAD];
static __device__ __align__(16) __half g_fl[MROWS * KPAD];
static __device__ __align__(16) __half g_gh[MROWS * KPAD];
static __device__ __align__(16) __half g_gl[MROWS * KPAD];
static __device__ __align__(16) __half g_th[(size_t)BATCH * CDIM * NPIX]; // hm^T fp16
static __device__ __align__(16) float  g_m[MROWS];                        // row maxes
static __device__ __align__(16) bf16   g_oh[MROWS * CDIM];
static __device__ __align__(16) bf16   g_ol[MROWS * CDIM];

// --- PTX helpers ------------------------------------------------------------
__device__ __forceinline__ uint32_t smem_u32(const void* p) {
    uint32_t a;
    asm("{ .reg .u64 t; cvta.to.shared.u64 t, %1; cvt.u32.u64 %0, t; }"
        : "=r"(a) : "l"(p));
    return a;
}

#define SWZ128(off) ((off) ^ (((off) >> 3) & 0x70u))

#define LDSM4(r, addr) \
    asm volatile("ldmatrix.sync.aligned.m8n8.x4.shared.b16 {%0,%1,%2,%3}, [%4];" \
        : "=r"((r)[0]), "=r"((r)[1]), "=r"((r)[2]), "=r"((r)[3]) : "r"(addr))

#define MMA16816(d, a, b0, b1) \
    asm volatile("mma.sync.aligned.m16n8k16.row.col.f32.bf16.bf16.f32 " \
        "{%0,%1,%2,%3}, {%4,%5,%6,%7}, {%8,%9}, {%0,%1,%2,%3};" \
        : "+f"((d)[0]), "+f"((d)[1]), "+f"((d)[2]), "+f"((d)[3]) \
        : "r"((a)[0]), "r"((a)[1]), "r"((a)[2]), "r"((a)[3]), "r"(b0), "r"(b1))

#define MMAH16816(d, a, b0, b1) \
    asm volatile("mma.sync.aligned.m16n8k16.row.col.f32.f16.f16.f32 " \
        "{%0,%1,%2,%3}, {%4,%5,%6,%7}, {%8,%9}, {%0,%1,%2,%3};" \
        : "+f"((d)[0]), "+f"((d)[1]), "+f"((d)[2]), "+f"((d)[3]) \
        : "r"((a)[0]), "r"((a)[1]), "r"((a)[2]), "r"((a)[3]), "r"(b0), "r"(b1))

#define CP16(smaddr, gptr) \
    asm volatile("cp.async.cg.shared.global [%0], [%1], 16;" \
        :: "r"(smaddr), "l"(gptr))
#define CP_COMMIT() asm volatile("cp.async.commit_group;" ::: "memory")
#define CP_WAIT1()  asm volatile("cp.async.wait_group 1;" ::: "memory")
#define CP_WAIT0()  asm volatile("cp.async.wait_group 0;" ::: "memory")

#define STS32(addr, v) \
    asm volatile("st.shared.b32 [%0], %1;" :: "r"(addr), "r"(v))

__device__ __forceinline__ float ex2f(float x) {
    float r; asm("ex2.approx.f32 %0, %1;" : "=f"(r) : "f"(x)); return r;
}
// bf16 pack (for o / projections path)
__device__ __forceinline__ uint32_t pack_hi(float a, float b) {
    __nv_bfloat162 h; h.x = __float2bfloat16(a); h.y = __float2bfloat16(b);
    return *(uint32_t*)&h;
}
__device__ __forceinline__ uint32_t pack_lo(float a, float b) {
    bf16 ha = __float2bfloat16(a), hb = __float2bfloat16(b);
    __nv_bfloat162 l;
    l.x = __float2bfloat16(a - __bfloat162float(ha));
    l.y = __float2bfloat16(b - __bfloat162float(hb));
    return *(uint32_t*)&l;
}
// fp16 pack (attention core)
__device__ __forceinline__ uint32_t packh_hi(float a, float b) {
    __half2 h = __floats2half2_rn(a, b);
    return *(uint32_t*)&h;
}
__device__ __forceinline__ uint32_t packh_lo(float a, float b) {
    float ra = __half2float(__float2half_rn(a));
    float rb = __half2float(__float2half_rn(b));
    __half2 l = __floats2half2_rn(a - ra, b - rb);
    return *(uint32_t*)&l;
}

// ---------------------------------------------------------------------------
// x -> split bf16 (hi/lo)
// ---------------------------------------------------------------------------
__global__ __launch_bounds__(256)
void xsplit_kernel(const float* __restrict__ X,
                   bf16* __restrict__ H, bf16* __restrict__ L)
{
    int i = blockIdx.x * 256 + threadIdx.x;
    float4 v = reinterpret_cast<const float4*>(X)[i];
    reinterpret_cast<uint32_t*>(H + (size_t)i * 4)[0] = pack_hi(v.x, v.y);
    reinterpret_cast<uint32_t*>(H + (size_t)i * 4)[1] = pack_hi(v.z, v.w);
    reinterpret_cast<uint32_t*>(L + (size_t)i * 4)[0] = pack_lo(v.x, v.y);
    reinterpret_cast<uint32_t*>(L + (size_t)i * 4)[1] = pack_lo(v.z, v.w);
}

// ---------------------------------------------------------------------------
// Weight prep: transpose + split (bf16).
// ---------------------------------------------------------------------------
__global__ __launch_bounds__(256)
void wprep_kernel(const float* __restrict__ Wf, const float* __restrict__ Wg,
                  const float* __restrict__ Wh, const float* __restrict__ Wv,
                  bf16* __restrict__ FGh, bf16* __restrict__ FGl,
                  bf16* __restrict__ WHh, bf16* __restrict__ WHl,
                  bf16* __restrict__ WVh, bf16* __restrict__ WVl)
{
    int r = blockIdx.x;
    int k = threadIdx.x;
    float w;
    bf16 *ph, *pl;
    int out;
    if (r < 64) {
        w = (r < 32) ? Wf[k * CKDIM + r] : Wg[k * CKDIM + (r - 32)];
        ph = FGh; pl = FGl; out = r * CDIM + k;
    } else if (r < 320) {
        int c = r - 64;
        w = Wh[k * CDIM + c];
        ph = WHh; pl = WHl; out = c * CDIM + k;
    } else {
        int c = r - 320;
        w = Wv[k * CDIM + c];
        ph = WVh; pl = WVl; out = c * CDIM + k;
    }
    bf16 h = __float2bfloat16(w);
    ph[out] = h;
    pl[out] = __float2bfloat16(w - __bfloat162float(h));
}

// ---------------------------------------------------------------------------
// Generic NT GEMM, bf16 split 3-term mainloop (proven).
// NMAP: 0 plain fp32/bf16-split out; 1 hm^T -> single fp16; 2 fg -> fp16 split
// ---------------------------------------------------------------------------
template<int NT, int OUT, int BIAS, int RES, int NMAP>
__global__ void __launch_bounds__(256, 1)
gemm_nt(const bf16* __restrict__ Ah, const bf16* __restrict__ Al, long long sA,
        const bf16* __restrict__ Bh, const bf16* __restrict__ Bl, long long sB,
        void* __restrict__ C0, void* __restrict__ C1,
        void* __restrict__ C2, void* __restrict__ C3,
        long long sC, int ldC,
        const float* __restrict__ bias, const float* __restrict__ bias2,
        const float* __restrict__ resid, int K)
{
    extern __shared__ __align__(1024) char gsm[];
    constexpr int AHo = 0;
    constexpr int ALo = 128 * 128;
    constexpr int BHo = 2 * 128 * 128;
    constexpr int BLo = BHo + NT * 128;
    constexpr int STG = BHo + 2 * NT * 128;

    const int t    = threadIdx.x;
    const int lane = t & 31;
    const int wid  = t >> 5;
    const int wm   = wid >> 1;
    const int wn   = wid & 1;
    const int m0   = blockIdx.x * 128;
    const int n0   = blockIdx.y * NT;
    const int z    = blockIdx.z;

    const uint32_t smb = smem_u32(gsm);
    const bf16* pAh = Ah + (size_t)z * sA + (size_t)m0 * K;
    const bf16* pAl = Al + (size_t)z * sA + (size_t)m0 * K;
    const bf16* pBh = Bh + (size_t)z * sB + (size_t)n0 * K;
    const bf16* pBl = Bl + (size_t)z * sB + (size_t)n0 * K;

    float acc[2][NT / 16][4];
    #pragma unroll
    for (int mt = 0; mt < 2; mt++)
      #pragma unroll
      for (int nt = 0; nt < NT / 16; nt++)
        #pragma unroll
        for (int q = 0; q < 4; q++)
            acc[mt][nt][q] = 0.f;

    auto load_stage = [&](int s, int c) {
        const uint32_t sb = smb + s * STG;
        const int k0 = c * 64;
        #pragma unroll
        for (int i = 0; i < 4; i++) {
            int idx = t + 256 * i;
            int row = idx >> 3, col = idx & 7;
            uint32_t off = SWZ128((uint32_t)(row * 128 + col * 16));
            CP16(sb + AHo + off, (const char*)(pAh + (size_t)row * K + k0) + col * 16);
            CP16(sb + ALo + off, (const char*)(pAl + (size_t)row * K + k0) + col * 16);
        }
        #pragma unroll
        for (int i = 0; i < NT / 32; i++) {
            int idx = t + 256 * i;
            int row = idx >> 3, col = idx & 7;
            uint32_t off = SWZ128((uint32_t)(row * 128 + col * 16));
            CP16(sb + BHo + off, (const char*)(pBh + (size_t)row * K + k0) + col * 16);
            CP16(sb + BLo + off, (const char*)(pBl + (size_t)row * K + k0) + col * 16);
        }
    };

    const int chunks = K >> 6;
    load_stage(0, 0);
    CP_COMMIT();

    for (int c = 0; c < chunks; ++c) {
        if (c + 1 < chunks) {
            load_stage((c + 1) & 1, c + 1);
            CP_COMMIT();
            CP_WAIT1();
        } else {
            CP_WAIT0();
        }
        __syncthreads();

        const uint32_t sb  = smb + (c & 1) * STG;
        const uint32_t sAh = sb + AHo, sAl = sb + ALo;
        const uint32_t sBh = sb + BHo, sBl = sb + BLo;

        #pragma unroll
        for (int ks = 0; ks < 4; ks++) {
            const uint32_t kbyte = ks * 32 + ((lane >> 4) << 4);

            uint32_t afh[2][4], afl[2][4];
            #pragma unroll
            for (int mt = 0; mt < 2; mt++) {
                int row = wm * 32 + mt * 16 + (lane & 15);
                uint32_t off = SWZ128((uint32_t)(row * 128) + kbyte);
                LDSM4(afh[mt], sAh + off);
                LDSM4(afl[mt], sAl + off);
            }

            #pragma unroll
            for (int ntp = 0; ntp < NT / 32; ntp++) {
                int row = wn * (NT / 2) + ntp * 16 + (lane & 15);
                uint32_t off = SWZ128((uint32_t)(row * 128) + kbyte);
                uint32_t bfh[4], bfl[4];
                LDSM4(bfh, sBh + off);
                LDSM4(bfl, sBl + off);
                #pragma unroll
                for (int h = 0; h < 2; h++) {
                    uint32_t b0h = h ? bfh[1] : bfh[0];
                    uint32_t b1h = h ? bfh[3] : bfh[2];
                    uint32_t b0l = h ? bfl[1] : bfl[0];
                    uint32_t b1l = h ? bfl[3] : bfl[2];
                    const int nt = ntp * 2 + h;
                    #pragma unroll
                    for (int mt = 0; mt < 2; mt++) {
                        MMA16816(acc[mt][nt], afh[mt], b0h, b1h);
                        MMA16816(acc[mt][nt], afh[mt], b0l, b1l);
                        MMA16816(acc[mt][nt], afl[mt], b0h, b1h);
                    }
                }
            }
        }
        __syncthreads();
    }

    const int g = lane >> 2;
    const int q = lane & 3;

    auto store2 = [&](int rg, int cg, float v0, float v1) {
        if constexpr (BIAS == 1) { v0 += bias[cg]; v1 += bias[cg + 1]; }
        if constexpr (BIAS == 2) { float bb = bias[rg]; v0 += bb; v1 += bb; }

        if constexpr (NMAP == 2) {
            // fg projection: emit fp16 split, zero-pad K 32..63
            bool isf = (cg < 32);
            float b0 = isf ? bias[cg]  : bias2[cg - 32];
            float b1 = isf ? bias[cg + 1] : bias2[cg - 31];
            v0 += b0; v1 += b1;
            uint32_t hp = packh_hi(v0, v1);
            uint32_t lp = packh_lo(v0, v1);
            size_t rowb = (size_t)rg * KPAD;
            if (isf) {
                *(uint32_t*)((__half*)C0 + rowb + cg) = hp;
                *(uint32_t*)((__half*)C1 + rowb + cg) = lp;
                *(uint32_t*)((__half*)C0 + rowb + cg + 32) = 0u;
                *(uint32_t*)((__half*)C1 + rowb + cg + 32) = 0u;
            } else {
                *(uint32_t*)((__half*)C2 + rowb + cg - 32) = hp;
                *(uint32_t*)((__half*)C3 + rowb + cg - 32) = lp;
                *(uint32_t*)((__half*)C2 + rowb + cg) = 0u;
                *(uint32_t*)((__half*)C3 + rowb + cg) = 0u;
            }
        } else if constexpr (NMAP == 1) {
            // hm^T: single fp16
            int bb = cg >> 12, nn = cg & 4095;
            size_t off = ((size_t)(bb * CDIM + rg)) * NPIX + nn;
            *(uint32_t*)((__half*)C0 + off) = packh_hi(v0, v1);
        } else if constexpr (OUT == 0) {
            size_t off = (size_t)z * sC + (size_t)rg * ldC + cg;
            if constexpr (RES) {
                v0 += resid[(size_t)rg * ldC + cg];
                v1 += resid[(size_t)rg * ldC + cg + 1];
            }
            *(float2*)((float*)C0 + off) = make_float2(v0, v1);
        } else {
            size_t off = (size_t)z * sC + (size_t)rg * ldC + cg;
            *(uint32_t*)((bf16*)C0 + off) = pack_hi(v0, v1);
            *(uint32_t*)((bf16*)C1 + off) = pack_lo(v0, v1);
        }
    };

    #pragma unroll
    for (int mt = 0; mt < 2; mt++) {
        #pragma unroll
        for (int nt = 0; nt < NT / 16; nt++) {
            int rg = m0 + wm * 32 + mt * 16 + g;
            int cg = n0 + wn * (NT / 2) + nt * 8 + q * 2;
            store2(rg,     cg, acc[mt][nt][0], acc[mt][nt][1]);
            store2(rg + 8, cg, acc[mt][nt][2], acc[mt][nt][3]);
        }
    }
}

// ---------------------------------------------------------------------------
// Pass A: per-row approx max of s = g @ f^T, 1-term fp16 (hi only).
// Any per-row constant error in m cancels in normalization.
// grid (32,1,4), 256 threads. Key chunks of 128.
// ---------------------------------------------------------------------------
#define RA_G 0
#define RA_ST(s) (16384 + (s) * 16384)
#define RA_SMEM  49152

__global__ void __launch_bounds__(256, 1)
rowmax_kernel(const __half* __restrict__ gh, const __half* __restrict__ fh,
              float* __restrict__ M)
{
    extern __shared__ __align__(1024) char rsm[];
    const int t = threadIdx.x, lane = t & 31, w = t >> 5;
    const int b = blockIdx.z, m0 = blockIdx.x * 128;
    const uint32_t smb = smem_u32(rsm);
    const uint32_t kb = (uint32_t)((lane >> 4) << 4);

    {
        const char* sH = (const char*)(gh + (size_t)(b * NPIX + m0) * KPAD);
        #pragma unroll
        for (int i = 0; i < 4; i++) {
            int idx = t + 256 * i;
            int row = idx >> 3, col = idx & 7;
            uint32_t off = SWZ128((uint32_t)(row * 128 + col * 16));
            CP16(smb + RA_G + off, sH + (size_t)row * 128 + col * 16);
        }
    }
    auto loadf = [&](int s, int c) {
        const int k0 = c * 128;
        const char* sH = (const char*)(fh + (size_t)(b * NPIX + k0) * KPAD);
        #pragma unroll
        for (int i = 0; i < 4; i++) {
            int idx = t + 256 * i;
            int row = idx >> 3, col = idx & 7;
            uint32_t off = SWZ128((uint32_t)(row * 128 + col * 16));
            CP16(smb + RA_ST(s) + off, sH + (size_t)row * 128 + col * 16);
        }
    };
    loadf(0, 0);
    CP_COMMIT();

    float mx0 = -3.4e38f, mx1 = -3.4e38f;

    for (int c = 0; c < 32; c++) {
        if (c + 1 < 32) { loadf((c + 1) & 1, c + 1); CP_COMMIT(); CP_WAIT1(); }
        else            { CP_WAIT0(); }
        __syncthreads();

        const uint32_t gH = smb + RA_G;
        const uint32_t fH = smb + RA_ST(c & 1);

        uint32_t ah[2][4];
        #pragma unroll
        for (int ks = 0; ks < 2; ks++) {
            uint32_t off = SWZ128((uint32_t)((16 * w + (lane & 15)) * 128) + ks * 32 + kb);
            LDSM4(ah[ks], gH + off);
        }
        #pragma unroll
        for (int ntp = 0; ntp < 8; ntp++) {
            float fr[2][4] = {{0.f,0.f,0.f,0.f},{0.f,0.f,0.f,0.f}};
            #pragma unroll
            for (int ks = 0; ks < 2; ks++) {
                uint32_t off = SWZ128((uint32_t)((ntp * 16 + (lane & 15)) * 128) + ks * 32 + kb);
                uint32_t bh[4];
                LDSM4(bh, fH + off);
                MMAH16816(fr[0], ah[ks], bh[0], bh[2]);
                MMAH16816(fr[1], ah[ks], bh[1], bh[3]);
            }
            #pragma unroll
            for (int h = 0; h < 2; h++) {
                mx0 = fmaxf(mx0, fmaxf(fr[h][0], fr[h][1]));
                mx1 = fmaxf(mx1, fmaxf(fr[h][2], fr[h][3]));
            }
        }
        __syncthreads();
    }

    mx0 = fmaxf(mx0, __shfl_xor_sync(~0u, mx0, 1));
    mx0 = fmaxf(mx0, __shfl_xor_sync(~0u, mx0, 2));
    mx1 = fmaxf(mx1, __shfl_xor_sync(~0u, mx1, 1));
    mx1 = fmaxf(mx1, __shfl_xor_sync(~0u, mx1, 2));
    if ((lane & 3) == 0) {
        int r = m0 + 16 * w + (lane >> 2);
        M[(size_t)b * NPIX + r]     = mx0;
        M[(size_t)b * NPIX + r + 8] = mx1;
    }
}

// ---------------------------------------------------------------------------
// Pass B: fused s -> exp -> o (unnormalized) -> normalize.  All fp16.
// s: 3-term split; p: fp16 hi only; o: 1-term p @ hm (hm single fp16).
// grid (32,1,4), 512 threads.
// ---------------------------------------------------------------------------
#define FB_G_HI 0
#define FB_G_LO 16384
#define FB_ST(s) (32768 + (s) * 49152)   // f_hi 8K, f_lo 8K, hm 32K
#define FB_P(s)  (131072 + (s) * 16384)  // p_hi 16K
#define FB_SMEM  163840

__global__ void __launch_bounds__(512, 1)
fused_attn_kernel(const __half* __restrict__ gh, const __half* __restrict__ gl,
                  const __half* __restrict__ fh, const __half* __restrict__ fl,
                  const __half* __restrict__ hmT,
                  const float* __restrict__ M,
                  bf16* __restrict__ oh, bf16* __restrict__ ol)
{
    extern __shared__ __align__(1024) char fsm[];
    __shared__ float rsum[2][128];
    const int t = threadIdx.x, lane = t & 31, w = t >> 5;
    const int wm = w >> 1, wn = w & 1;
    const int b = blockIdx.z, m0 = blockIdx.x * 128;
    const int g = lane >> 2, q = lane & 3;
    const uint32_t smb = smem_u32(fsm);
    const uint32_t kb = (uint32_t)((lane >> 4) << 4);
    const float l2e = 1.4426950408889634f;

    const float mc0 = M[(size_t)b * NPIX + m0 + 16 * wm + g] * l2e;
    const float mc1 = M[(size_t)b * NPIX + m0 + 16 * wm + 8 + g] * l2e;

    {
        const char* sH = (const char*)(gh + (size_t)(b * NPIX + m0) * KPAD);
        const char* sL = (const char*)(gl + (size_t)(b * NPIX + m0) * KPAD);
        #pragma unroll
        for (int i = 0; i < 2; i++) {
            int idx = t + 512 * i;
            int row = idx >> 3, col = idx & 7;
            uint32_t off = SWZ128((uint32_t)(row * 128 + col * 16));
            CP16(smb + FB_G_HI + off, sH + (size_t)row * 128 + col * 16);
            CP16(smb + FB_G_LO + off, sL + (size_t)row * 128 + col * 16);
        }
    }
    auto loadc = [&](int s, int c) {
        const int k0 = c * 64;
        {
            int row = t >> 3, col = t & 7;
            uint32_t off = SWZ128((uint32_t)(row * 128 + col * 16));
            CP16(smb + FB_ST(s) + off,
                 (const char*)(fh + (size_t)(b * NPIX + k0 + row) * KPAD) + col * 16);
            CP16(smb + FB_ST(s) + 8192 + off,
                 (const char*)(fl + (size_t)(b * NPIX + k0 + row) * KPAD) + col * 16);
        }
        #pragma unroll
        for (int i = 0; i < 4; i++) {
            int idx = t + 512 * i;
            int row = idx >> 3, col = idx & 7;
            uint32_t off = SWZ128((uint32_t)(row * 128 + col * 16));
            CP16(smb + FB_ST(s) + 16384 + off,
                 (const char*)(hmT + ((size_t)(b * CDIM + row) * NPIX + k0)) + col * 16);
        }
    };
    loadc(0, 0);
    CP_COMMIT();

    float acc[16][4];
    #pragma unroll
    for (int nt = 0; nt < 16; nt++)
        #pragma unroll
        for (int i = 0; i < 4; i++) acc[nt][i] = 0.f;
    float sum0 = 0.f, sum1 = 0.f;

    for (int c = 0; c < 64; c++) {
        CP_WAIT0();
        __syncthreads();

        const uint32_t gH = smb + FB_G_HI, gL = smb + FB_G_LO;
        const uint32_t stb = smb + FB_ST(c & 1);
        const uint32_t fH = stb, fL = stb + 8192, hmS = stb + 16384;
        const uint32_t pH = smb + FB_P(c & 1);

        // ---- s-phase: rows 16wm x keys [32wn, 32wn+32), 3-term fp16 ----
        {
            uint32_t ah[2][4], al[2][4];
            #pragma unroll
            for (int ks = 0; ks < 2; ks++) {
                uint32_t off = SWZ128((uint32_t)((16 * wm + (lane & 15)) * 128) + ks * 32 + kb);
                LDSM4(ah[ks], gH + off);
                LDSM4(al[ks], gL + off);
            }
            #pragma unroll
            for (int ntp = 0; ntp < 2; ntp++) {
                float fr[2][4] = {{0.f,0.f,0.f,0.f},{0.f,0.f,0.f,0.f}};
                #pragma unroll
                for (int ks = 0; ks < 2; ks++) {
                    uint32_t off = SWZ128((uint32_t)((32 * wn + ntp * 16 + (lane & 15)) * 128)
                                          + ks * 32 + kb);
                    uint32_t bh[4], bl[4];
                    LDSM4(bh, fH + off);
                    LDSM4(bl, fL + off);
                    #pragma unroll
                    for (int h = 0; h < 2; h++) {
                        uint32_t b0h = h ? bh[1] : bh[0], b1h = h ? bh[3] : bh[2];
                        uint32_t b0l = h ? bl[1] : bl[0], b1l = h ? bl[3] : bl[2];
                        MMAH16816(fr[h], ah[ks], b0h, b1h);
                        MMAH16816(fr[h], ah[ks], b0l, b1l);
                        MMAH16816(fr[h], al[ks], b0h, b1h);
                    }
                }
                #pragma unroll
                for (int h = 0; h < 2; h++) {
                    int key = 32 * wn + ntp * 16 + h * 8 + 2 * q;
                    float p0 = ex2f(fmaf(fr[h][0], l2e, -mc0));
                    float p1 = ex2f(fmaf(fr[h][1], l2e, -mc0));
                    float p2 = ex2f(fmaf(fr[h][2], l2e, -mc1));
                    float p3 = ex2f(fmaf(fr[h][3], l2e, -mc1));
                    sum0 += p0 + p1;
                    sum1 += p2 + p3;
                    uint32_t a0 = SWZ128((uint32_t)((16 * wm + g) * 128 + key * 2));
                    uint32_t a1 = SWZ128((uint32_t)((16 * wm + 8 + g) * 128 + key * 2));
                    STS32(pH + a0, packh_hi(p0, p1));
                    STS32(pH + a1, packh_hi(p2, p3));
                }
            }
        }
        __syncthreads();

        if (c + 1 < 64) { loadc((c + 1) & 1, c + 1); CP_COMMIT(); }

        // ---- o-phase: rows 16wm x channels [128wn, 128wn+128), 1-term ----
        #pragma unroll
        for (int ks = 0; ks < 4; ks++) {
            uint32_t offA = SWZ128((uint32_t)((16 * wm + (lane & 15)) * 128) + ks * 32 + kb);
            uint32_t aph[4];
            LDSM4(aph, pH + offA);
            #pragma unroll
            for (int ntp = 0; ntp < 8; ntp++) {
                uint32_t off = SWZ128((uint32_t)((128 * wn + ntp * 16 + (lane & 15)) * 128)
                                      + ks * 32 + kb);
                uint32_t bh[4];
                LDSM4(bh, hmS + off);
                MMAH16816(acc[ntp * 2 + 0], aph, bh[0], bh[2]);
                MMAH16816(acc[ntp * 2 + 1], aph, bh[1], bh[3]);
            }
        }
    }

    // ---- normalize + store o split-bf16 ----
    sum0 += __shfl_xor_sync(~0u, sum0, 1);
    sum0 += __shfl_xor_sync(~0u, sum0, 2);
    sum1 += __shfl_xor_sync(~0u, sum1, 1);
    sum1 += __shfl_xor_sync(~0u, sum1, 2);
    if ((lane & 3) == 0) {
        rsum[wn][16 * wm + g] = sum0;
        rsum[wn][16 * wm + 8 + g] = sum1;
    }
    __syncthreads();
    const float inv0 = 1.f / (rsum[0][16 * wm + g]     + rsum[1][16 * wm + g]);
    const float inv1 = 1.f / (rsum[0][16 * wm + 8 + g] + rsum[1][16 * wm + 8 + g]);

    #pragma unroll
    for (int nt = 0; nt < 16; nt++) {
        int ch = 128 * wn + nt * 8 + 2 * q;
        float v0 = acc[nt][0] * inv0, v1 = acc[nt][1] * inv0;
        float v2 = acc[nt][2] * inv1, v3 = acc[nt][3] * inv1;
        size_t o0 = ((size_t)(b * NPIX + m0 + 16 * wm + g)) * CDIM + ch;
        size_t o1 = ((size_t)(b * NPIX + m0 + 16 * wm + 8 + g)) * CDIM + ch;
        *(uint32_t*)(oh + o0) = pack_hi(v0, v1);
        *(uint32_t*)(ol + o0) = pack_lo(v0, v1);
        *(uint32_t*)(oh + o1) = pack_hi(v2, v3);
        *(uint32_t*)(ol + o1) = pack_lo(v2, v3);
    }
}

// ---------------------------------------------------------------------------
extern "C" void kernel_launch(void* const* d_in, const int* in_sizes, int n_in,
                              void* d_out, int out_size)
{
    (void)in_sizes; (void)n_in; (void)out_size;
    const float* x  = (const float*)d_in[0];
    const float* Wf = (const float*)d_in[1];
    const float* bf = (const float*)d_in[2];
    const float* Wg = (const float*)d_in[3];
    const float* bg = (const float*)d_in[4];
    const float* Wh = (const float*)d_in[5];
    const float* bh = (const float*)d_in[6];
    const float* Wv = (const float*)d_in[7];
    const float* bv = (const float*)d_in[8];
    float* out = (float*)d_out;

    bf16 *xh, *xl, *fgth, *fgtl, *whth, *whtl, *wvth, *wvtl, *oh, *ol;
    __half *fh, *fl, *gh, *gl, *th;
    float* pm;
    cudaGetSymbolAddress((void**)&xh,   g_xh);
    cudaGetSymbolAddress((void**)&xl,   g_xl);
    cudaGetSymbolAddress((void**)&fgth, g_wfgt_h);
    cudaGetSymbolAddress((void**)&fgtl, g_wfgt_l);
    cudaGetSymbolAddress((void**)&whth, g_wht_h);
    cudaGetSymbolAddress((void**)&whtl, g_wht_l);
    cudaGetSymbolAddress((void**)&wvth, g_wvt_h);
    cudaGetSymbolAddress((void**)&wvtl, g_wvt_l);
    cudaGetSymbolAddress((void**)&fh,   g_fh);
    cudaGetSymbolAddress((void**)&fl,   g_fl);
    cudaGetSymbolAddress((void**)&gh,   g_gh);
    cudaGetSymbolAddress((void**)&gl,   g_gl);
    cudaGetSymbolAddress((void**)&th,   g_th);
    cudaGetSymbolAddress((void**)&pm,   g_m);
    cudaGetSymbolAddress((void**)&oh,   g_oh);
    cudaGetSymbolAddress((void**)&ol,   g_ol);

    const int SM128 = 2 * (2 * 128 * 128 + 2 * 128 * 128);
    const int SM64  = 2 * (2 * 128 * 128 + 2 * 64 * 128);
    cudaFuncSetAttribute(gemm_nt<64, 1, 0, 0, 2>,
                         cudaFuncAttributeMaxDynamicSharedMemorySize, SM64);
    cudaFuncSetAttribute(gemm_nt<128, 1, 2, 0, 1>,
                         cudaFuncAttributeMaxDynamicSharedMemorySize, SM128);
    cudaFuncSetAttribute(gemm_nt<128, 0, 1, 1, 0>,
                         cudaFuncAttributeMaxDynamicSharedMemorySize, SM128);
    cudaFuncSetAttribute(rowmax_kernel,
                         cudaFuncAttributeMaxDynamicSharedMemorySize, RA_SMEM);
    cudaFuncSetAttribute(fused_attn_kernel,
                         cudaFuncAttributeMaxDynamicSharedMemorySize, FB_SMEM);

    dim3 blk(256);

    // prep: x split + weight transpose/split
    xsplit_kernel<<<MROWS * CDIM / 4 / 256, blk>>>(x, xh, xl);
    wprep_kernel<<<576, blk>>>(Wf, Wg, Wh, Wv,
                               fgth, fgtl, whth, whtl, wvth, wvtl);

    // fg proj: f,g split fp16 (K padded to 64)
    gemm_nt<64, 1, 0, 0, 2><<<dim3(MROWS / 128, 1, 1), blk, SM64>>>(
        xh, xl, 0, fgth, fgtl, 0,
        fh, fl, gh, gl, 0, KPAD, bf, bg, nullptr, CDIM);

    // hm^T proj: single fp16, bias on rows
    gemm_nt<128, 1, 2, 0, 1><<<dim3(CDIM / 128, MROWS / 128, 1), blk, SM128>>>(
        whth, whtl, 0, xh, xl, 0,
        th, nullptr, nullptr, nullptr, 0, 0, bh, nullptr, nullptr, CDIM);

    // pass A: approx row maxes of s (1-term fp16)
    rowmax_kernel<<<dim3(NPIX / 128, 1, BATCH), blk, RA_SMEM>>>(gh, fh, pm);

    // pass B: fused exp + o (unnormalized) + normalize -> o split bf16
    fused_attn_kernel<<<dim3(NPIX / 128, 1, BATCH), dim3(512), FB_SMEM>>>(
        gh, gl, fh, fl, th, pm, oh, ol);

    // out = x + o @ Wv + bv (fp32)
    gemm_nt<128, 0, 1, 1, 0><<<dim3(MROWS / 128, CDIM / 128, 1), blk, SM128>>>(
        oh, ol, 0, wvth, wvtl, 0,
        out, nullptr, nullptr, nullptr, 0, CDIM, bv, nullptr, x, CDIM);
}

// round 16
// speedup vs baseline: 4.5814x; 1.0656x over previous
#include <cuda_runtime.h>
#include <cuda_bf16.h>
#include <cuda_fp16.h>
#include <cstdint>

// ---------------------------------------------------------------------------
// SelfAttention (SAGAN-style), B=4, N=4096, C=256, Ck=32.
// Projections / v-proj: bf16 split 3-term mma.sync, MT=64 tiles (2 CTAs/SM).
// Attention core fp16:
//   pass A (rowmax): 1-term fp16 (per-row-constant error cancels)
//   pass B (fused): s = 2-term fp16 (g_hi f_hi + g_lo f_hi; f_lo eliminated);
//                   p = exp fp16 hi; o += p @ hm, hm single fp16 (1 term).
// ---------------------------------------------------------------------------

#define BATCH 4
#define NPIX  4096
#define CDIM  256
#define CKDIM 32
#define MROWS 16384
#define KPAD  64

typedef __nv_bfloat16 bf16;

static __device__ __align__(16) bf16   g_xh[MROWS * CDIM];
static __device__ __align__(16) bf16   g_xl[MROWS * CDIM];
static __device__ __align__(16) bf16   g_wfgt_h[64 * CDIM];
static __device__ __align__(16) bf16   g_wfgt_l[64 * CDIM];
static __device__ __align__(16) bf16   g_wht_h[CDIM * CDIM];
static __device__ __align__(16) bf16   g_wht_l[CDIM * CDIM];
static __device__ __align__(16) bf16   g_wvt_h[CDIM * CDIM];
static __device__ __align__(16) bf16   g_wvt_l[CDIM * CDIM];
static __device__ __align__(16) __half g_fh[MROWS * KPAD];
static __device__ __align__(16) __half g_fl[MROWS * KPAD];   // written, unused
static __device__ __align__(16) __half g_gh[MROWS * KPAD];
static __device__ __align__(16) __half g_gl[MROWS * KPAD];
static __device__ __align__(16) __half g_th[(size_t)BATCH * CDIM * NPIX];
static __device__ __align__(16) float  g_m[MROWS];
static __device__ __align__(16) bf16   g_oh[MROWS * CDIM];
static __device__ __align__(16) bf16   g_ol[MROWS * CDIM];

// --- PTX helpers ------------------------------------------------------------
__device__ __forceinline__ uint32_t smem_u32(const void* p) {
    uint32_t a;
    asm("{ .reg .u64 t; cvta.to.shared.u64 t, %1; cvt.u32.u64 %0, t; }"
        : "=r"(a) : "l"(p));
    return a;
}

#define SWZ128(off) ((off) ^ (((off) >> 3) & 0x70u))

#define LDSM4(r, addr) \
    asm volatile("ldmatrix.sync.aligned.m8n8.x4.shared.b16 {%0,%1,%2,%3}, [%4];" \
        : "=r"((r)[0]), "=r"((r)[1]), "=r"((r)[2]), "=r"((r)[3]) : "r"(addr))

#define MMA16816(d, a, b0, b1) \
    asm volatile("mma.sync.aligned.m16n8k16.row.col.f32.bf16.bf16.f32 " \
        "{%0,%1,%2,%3}, {%4,%5,%6,%7}, {%8,%9}, {%0,%1,%2,%3};" \
        : "+f"((d)[0]), "+f"((d)[1]), "+f"((d)[2]), "+f"((d)[3]) \
        : "r"((a)[0]), "r"((a)[1]), "r"((a)[2]), "r"((a)[3]), "r"(b0), "r"(b1))

#define MMAH16816(d, a, b0, b1) \
    asm volatile("mma.sync.aligned.m16n8k16.row.col.f32.f16.f16.f32 " \
        "{%0,%1,%2,%3}, {%4,%5,%6,%7}, {%8,%9}, {%0,%1,%2,%3};" \
        : "+f"((d)[0]), "+f"((d)[1]), "+f"((d)[2]), "+f"((d)[3]) \
        : "r"((a)[0]), "r"((a)[1]), "r"((a)[2]), "r"((a)[3]), "r"(b0), "r"(b1))

#define CP16(smaddr, gptr) \
    asm volatile("cp.async.cg.shared.global [%0], [%1], 16;" \
        :: "r"(smaddr), "l"(gptr))
#define CP_COMMIT() asm volatile("cp.async.commit_group;" ::: "memory")
#define CP_WAIT1()  asm volatile("cp.async.wait_group 1;" ::: "memory")
#define CP_WAIT0()  asm volatile("cp.async.wait_group 0;" ::: "memory")

#define STS32(addr, v) \
    asm volatile("st.shared.b32 [%0], %1;" :: "r"(addr), "r"(v))

__device__ __forceinline__ float ex2f(float x) {
    float r; asm("ex2.approx.f32 %0, %1;" : "=f"(r) : "f"(x)); return r;
}
__device__ __forceinline__ uint32_t pack_hi(float a, float b) {
    __nv_bfloat162 h; h.x = __float2bfloat16(a); h.y = __float2bfloat16(b);
    return *(uint32_t*)&h;
}
__device__ __forceinline__ uint32_t pack_lo(float a, float b) {
    bf16 ha = __float2bfloat16(a), hb = __float2bfloat16(b);
    __nv_bfloat162 l;
    l.x = __float2bfloat16(a - __bfloat162float(ha));
    l.y = __float2bfloat16(b - __bfloat162float(hb));
    return *(uint32_t*)&l;
}
__device__ __forceinline__ uint32_t packh_hi(float a, float b) {
    __half2 h = __floats2half2_rn(a, b);
    return *(uint32_t*)&h;
}
__device__ __forceinline__ uint32_t packh_lo(float a, float b) {
    float ra = __half2float(__float2half_rn(a));
    float rb = __half2float(__float2half_rn(b));
    __half2 l = __floats2half2_rn(a - ra, b - rb);
    return *(uint32_t*)&l;
}

// ---------------------------------------------------------------------------
__global__ __launch_bounds__(256)
void xsplit_kernel(const float* __restrict__ X,
                   bf16* __restrict__ H, bf16* __restrict__ L)
{
    int i = blockIdx.x * 256 + threadIdx.x;
    float4 v = reinterpret_cast<const float4*>(X)[i];
    reinterpret_cast<uint32_t*>(H + (size_t)i * 4)[0] = pack_hi(v.x, v.y);
    reinterpret_cast<uint32_t*>(H + (size_t)i * 4)[1] = pack_hi(v.z, v.w);
    reinterpret_cast<uint32_t*>(L + (size_t)i * 4)[0] = pack_lo(v.x, v.y);
    reinterpret_cast<uint32_t*>(L + (size_t)i * 4)[1] = pack_lo(v.z, v.w);
}

// ---------------------------------------------------------------------------
__global__ __launch_bounds__(256)
void wprep_kernel(const float* __restrict__ Wf, const float* __restrict__ Wg,
                  const float* __restrict__ Wh, const float* __restrict__ Wv,
                  bf16* __restrict__ FGh, bf16* __restrict__ FGl,
                  bf16* __restrict__ WHh, bf16* __restrict__ WHl,
                  bf16* __restrict__ WVh, bf16* __restrict__ WVl)
{
    int r = blockIdx.x;
    int k = threadIdx.x;
    float w;
    bf16 *ph, *pl;
    int out;
    if (r < 64) {
        w = (r < 32) ? Wf[k * CKDIM + r] : Wg[k * CKDIM + (r - 32)];
        ph = FGh; pl = FGl; out = r * CDIM + k;
    } else if (r < 320) {
        int c = r - 64;
        w = Wh[k * CDIM + c];
        ph = WHh; pl = WHl; out = c * CDIM + k;
    } else {
        int c = r - 320;
        w = Wv[k * CDIM + c];
        ph = WVh; pl = WVl; out = c * CDIM + k;
    }
    bf16 h = __float2bfloat16(w);
    ph[out] = h;
    pl[out] = __float2bfloat16(w - __bfloat162float(h));
}

// ---------------------------------------------------------------------------
// Generic NT GEMM, bf16 split 3-term.  MT in {64,128}, threads = 2*MT.
// MT=64 -> 2 CTAs/SM.
// ---------------------------------------------------------------------------
template<int MT, int NT, int OUT, int BIAS, int RES, int NMAP>
__global__ void __launch_bounds__(MT * 2, (MT == 64) ? 2 : 1)
gemm_nt(const bf16* __restrict__ Ah, const bf16* __restrict__ Al, long long sA,
        const bf16* __restrict__ Bh, const bf16* __restrict__ Bl, long long sB,
        void* __restrict__ C0, void* __restrict__ C1,
        void* __restrict__ C2, void* __restrict__ C3,
        long long sC, int ldC,
        const float* __restrict__ bias, const float* __restrict__ bias2,
        const float* __restrict__ resid, int K)
{
    extern __shared__ __align__(1024) char gsm[];
    constexpr int THREADS = MT * 2;
    constexpr int AHo = 0;
    constexpr int ALo = MT * 128;
    constexpr int BHo = 2 * MT * 128;
    constexpr int BLo = BHo + NT * 128;
    constexpr int STG = BHo + 2 * NT * 128;
    constexpr int BI  = (NT * 8) / THREADS;

    const int t    = threadIdx.x;
    const int lane = t & 31;
    const int wid  = t >> 5;
    const int wm   = wid >> 1;
    const int wn   = wid & 1;
    const int m0   = blockIdx.x * MT;
    const int n0   = blockIdx.y * NT;
    const int z    = blockIdx.z;

    const uint32_t smb = smem_u32(gsm);
    const bf16* pAh = Ah + (size_t)z * sA + (size_t)m0 * K;
    const bf16* pAl = Al + (size_t)z * sA + (size_t)m0 * K;
    const bf16* pBh = Bh + (size_t)z * sB + (size_t)n0 * K;
    const bf16* pBl = Bl + (size_t)z * sB + (size_t)n0 * K;

    float acc[2][NT / 16][4];
    #pragma unroll
    for (int mt = 0; mt < 2; mt++)
      #pragma unroll
      for (int nt = 0; nt < NT / 16; nt++)
        #pragma unroll
        for (int q = 0; q < 4; q++)
            acc[mt][nt][q] = 0.f;

    auto load_stage = [&](int s, int c) {
        const uint32_t sb = smb + s * STG;
        const int k0 = c * 64;
        #pragma unroll
        for (int i = 0; i < 4; i++) {
            int idx = t + THREADS * i;
            int row = idx >> 3, col = idx & 7;
            uint32_t off = SWZ128((uint32_t)(row * 128 + col * 16));
            CP16(sb + AHo + off, (const char*)(pAh + (size_t)row * K + k0) + col * 16);
            CP16(sb + ALo + off, (const char*)(pAl + (size_t)row * K + k0) + col * 16);
        }
        #pragma unroll
        for (int i = 0; i < BI; i++) {
            int idx = t + THREADS * i;
            int row = idx >> 3, col = idx & 7;
            uint32_t off = SWZ128((uint32_t)(row * 128 + col * 16));
            CP16(sb + BHo + off, (const char*)(pBh + (size_t)row * K + k0) + col * 16);
            CP16(sb + BLo + off, (const char*)(pBl + (size_t)row * K + k0) + col * 16);
        }
    };

    const int chunks = K >> 6;
    load_stage(0, 0);
    CP_COMMIT();

    for (int c = 0; c < chunks; ++c) {
        if (c + 1 < chunks) {
            load_stage((c + 1) & 1, c + 1);
            CP_COMMIT();
            CP_WAIT1();
        } else {
            CP_WAIT0();
        }
        __syncthreads();

        const uint32_t sb  = smb + (c & 1) * STG;
        const uint32_t sAh = sb + AHo, sAl = sb + ALo;
        const uint32_t sBh = sb + BHo, sBl = sb + BLo;

        #pragma unroll
        for (int ks = 0; ks < 4; ks++) {
            const uint32_t kbyte = ks * 32 + ((lane >> 4) << 4);

            uint32_t afh[2][4], afl[2][4];
            #pragma unroll
            for (int mt = 0; mt < 2; mt++) {
                int row = wm * 32 + mt * 16 + (lane & 15);
                uint32_t off = SWZ128((uint32_t)(row * 128) + kbyte);
                LDSM4(afh[mt], sAh + off);
                LDSM4(afl[mt], sAl + off);
            }

            #pragma unroll
            for (int ntp = 0; ntp < NT / 32; ntp++) {
                int row = wn * (NT / 2) + ntp * 16 + (lane & 15);
                uint32_t off = SWZ128((uint32_t)(row * 128) + kbyte);
                uint32_t bfh[4], bfl[4];
                LDSM4(bfh, sBh + off);
                LDSM4(bfl, sBl + off);
                #pragma unroll
                for (int h = 0; h < 2; h++) {
                    uint32_t b0h = h ? bfh[1] : bfh[0];
                    uint32_t b1h = h ? bfh[3] : bfh[2];
                    uint32_t b0l = h ? bfl[1] : bfl[0];
                    uint32_t b1l = h ? bfl[3] : bfl[2];
                    const int nt = ntp * 2 + h;
                    #pragma unroll
                    for (int mt = 0; mt < 2; mt++) {
                        MMA16816(acc[mt][nt], afh[mt], b0h, b1h);
                        MMA16816(acc[mt][nt], afh[mt], b0l, b1l);
                        MMA16816(acc[mt][nt], afl[mt], b0h, b1h);
                    }
                }
            }
        }
        __syncthreads();
    }

    const int g = lane >> 2;
    const int q = lane & 3;

    auto store2 = [&](int rg, int cg, float v0, float v1) {
        if constexpr (BIAS == 1) { v0 += bias[cg]; v1 += bias[cg + 1]; }
        if constexpr (BIAS == 2) { float bb = bias[rg]; v0 += bb; v1 += bb; }

        if constexpr (NMAP == 2) {
            bool isf = (cg < 32);
            float b0 = isf ? bias[cg]  : bias2[cg - 32];
            float b1 = isf ? bias[cg + 1] : bias2[cg - 31];
            v0 += b0; v1 += b1;
            uint32_t hp = packh_hi(v0, v1);
            uint32_t lp = packh_lo(v0, v1);
            size_t rowb = (size_t)rg * KPAD;
            if (isf) {
                *(uint32_t*)((__half*)C0 + rowb + cg) = hp;
                *(uint32_t*)((__half*)C1 + rowb + cg) = lp;
                *(uint32_t*)((__half*)C0 + rowb + cg + 32) = 0u;
                *(uint32_t*)((__half*)C1 + rowb + cg + 32) = 0u;
            } else {
                *(uint32_t*)((__half*)C2 + rowb + cg - 32) = hp;
                *(uint32_t*)((__half*)C3 + rowb + cg - 32) = lp;
                *(uint32_t*)((__half*)C2 + rowb + cg) = 0u;
                *(uint32_t*)((__half*)C3 + rowb + cg) = 0u;
            }
        } else if constexpr (NMAP == 1) {
            int bb = cg >> 12, nn = cg & 4095;
            size_t off = ((size_t)(bb * CDIM + rg)) * NPIX + nn;
            *(uint32_t*)((__half*)C0 + off) = packh_hi(v0, v1);
        } else if constexpr (OUT == 0) {
            size_t off = (size_t)z * sC + (size_t)rg * ldC + cg;
            if constexpr (RES) {
                v0 += resid[(size_t)rg * ldC + cg];
                v1 += resid[(size_t)rg * ldC + cg + 1];
            }
            *(float2*)((float*)C0 + off) = make_float2(v0, v1);
        } else {
            size_t off = (size_t)z * sC + (size_t)rg * ldC + cg;
            *(uint32_t*)((bf16*)C0 + off) = pack_hi(v0, v1);
            *(uint32_t*)((bf16*)C1 + off) = pack_lo(v0, v1);
        }
    };

    #pragma unroll
    for (int mt = 0; mt < 2; mt++) {
        #pragma unroll
        for (int nt = 0; nt < NT / 16; nt++) {
            int rg = m0 + wm * 32 + mt * 16 + g;
            int cg = n0 + wn * (NT / 2) + nt * 8 + q * 2;
            store2(rg,     cg, acc[mt][nt][0], acc[mt][nt][1]);
            store2(rg + 8, cg, acc[mt][nt][2], acc[mt][nt][3]);
        }
    }
}

// ---------------------------------------------------------------------------
// Pass A: per-row approx max of s, 1-term fp16.
// ---------------------------------------------------------------------------
#define RA_G 0
#define RA_ST(s) (16384 + (s) * 16384)
#define RA_SMEM  49152

__global__ void __launch_bounds__(256, 1)
rowmax_kernel(const __half* __restrict__ gh, const __half* __restrict__ fh,
              float* __restrict__ M)
{
    extern __shared__ __align__(1024) char rsm[];
    const int t = threadIdx.x, lane = t & 31, w = t >> 5;
    const int b = blockIdx.z, m0 = blockIdx.x * 128;
    const uint32_t smb = smem_u32(rsm);
    const uint32_t kb = (uint32_t)((lane >> 4) << 4);

    {
        const char* sH = (const char*)(gh + (size_t)(b * NPIX + m0) * KPAD);
        #pragma unroll
        for (int i = 0; i < 4; i++) {
            int idx = t + 256 * i;
            int row = idx >> 3, col = idx & 7;
            uint32_t off = SWZ128((uint32_t)(row * 128 + col * 16));
            CP16(smb + RA_G + off, sH + (size_t)row * 128 + col * 16);
        }
    }
    auto loadf = [&](int s, int c) {
        const int k0 = c * 128;
        const char* sH = (const char*)(fh + (size_t)(b * NPIX + k0) * KPAD);
        #pragma unroll
        for (int i = 0; i < 4; i++) {
            int idx = t + 256 * i;
            int row = idx >> 3, col = idx & 7;
            uint32_t off = SWZ128((uint32_t)(row * 128 + col * 16));
            CP16(smb + RA_ST(s) + off, sH + (size_t)row * 128 + col * 16);
        }
    };
    loadf(0, 0);
    CP_COMMIT();

    float mx0 = -3.4e38f, mx1 = -3.4e38f;

    for (int c = 0; c < 32; c++) {
        if (c + 1 < 32) { loadf((c + 1) & 1, c + 1); CP_COMMIT(); CP_WAIT1(); }
        else            { CP_WAIT0(); }
        __syncthreads();

        const uint32_t gH = smb + RA_G;
        const uint32_t fH = smb + RA_ST(c & 1);

        uint32_t ah[2][4];
        #pragma unroll
        for (int ks = 0; ks < 2; ks++) {
            uint32_t off = SWZ128((uint32_t)((16 * w + (lane & 15)) * 128) + ks * 32 + kb);
            LDSM4(ah[ks], gH + off);
        }
        #pragma unroll
        for (int ntp = 0; ntp < 8; ntp++) {
            float fr[2][4] = {{0.f,0.f,0.f,0.f},{0.f,0.f,0.f,0.f}};
            #pragma unroll
            for (int ks = 0; ks < 2; ks++) {
                uint32_t off = SWZ128((uint32_t)((ntp * 16 + (lane & 15)) * 128) + ks * 32 + kb);
                uint32_t bh[4];
                LDSM4(bh, fH + off);
                MMAH16816(fr[0], ah[ks], bh[0], bh[2]);
                MMAH16816(fr[1], ah[ks], bh[1], bh[3]);
            }
            #pragma unroll
            for (int h = 0; h < 2; h++) {
                mx0 = fmaxf(mx0, fmaxf(fr[h][0], fr[h][1]));
                mx1 = fmaxf(mx1, fmaxf(fr[h][2], fr[h][3]));
            }
        }
        __syncthreads();
    }

    mx0 = fmaxf(mx0, __shfl_xor_sync(~0u, mx0, 1));
    mx0 = fmaxf(mx0, __shfl_xor_sync(~0u, mx0, 2));
    mx1 = fmaxf(mx1, __shfl_xor_sync(~0u, mx1, 1));
    mx1 = fmaxf(mx1, __shfl_xor_sync(~0u, mx1, 2));
    if ((lane & 3) == 0) {
        int r = m0 + 16 * w + (lane >> 2);
        M[(size_t)b * NPIX + r]     = mx0;
        M[(size_t)b * NPIX + r + 8] = mx1;
    }
}

// ---------------------------------------------------------------------------
// Pass B: fused s -> exp -> o -> normalize.  fp16 core, s 2-term.
// ---------------------------------------------------------------------------
#define FB_G_HI 0
#define FB_G_LO 16384
#define FB_ST(s) (32768 + (s) * 40960)   // f_hi 8K, hm 32K
#define FB_P(s)  (114688 + (s) * 16384)  // p_hi 16K
#define FB_SMEM  147456

__global__ void __launch_bounds__(512, 1)
fused_attn_kernel(const __half* __restrict__ gh, const __half* __restrict__ gl,
                  const __half* __restrict__ fh,
                  const __half* __restrict__ hmT,
                  const float* __restrict__ M,
                  bf16* __restrict__ oh, bf16* __restrict__ ol)
{
    extern __shared__ __align__(1024) char fsm[];
    __shared__ float rsum[2][128];
    const int t = threadIdx.x, lane = t & 31, w = t >> 5;
    const int wm = w >> 1, wn = w & 1;
    const int b = blockIdx.z, m0 = blockIdx.x * 128;
    const int g = lane >> 2, q = lane & 3;
    const uint32_t smb = smem_u32(fsm);
    const uint32_t kb = (uint32_t)((lane >> 4) << 4);
    const float l2e = 1.4426950408889634f;

    const float mc0 = M[(size_t)b * NPIX + m0 + 16 * wm + g] * l2e;
    const float mc1 = M[(size_t)b * NPIX + m0 + 16 * wm + 8 + g] * l2e;

    {
        const char* sH = (const char*)(gh + (size_t)(b * NPIX + m0) * KPAD);
        const char* sL = (const char*)(gl + (size_t)(b * NPIX + m0) * KPAD);
        #pragma unroll
        for (int i = 0; i < 2; i++) {
            int idx = t + 512 * i;
            int row = idx >> 3, col = idx & 7;
            uint32_t off = SWZ128((uint32_t)(row * 128 + col * 16));
            CP16(smb + FB_G_HI + off, sH + (size_t)row * 128 + col * 16);
            CP16(smb + FB_G_LO + off, sL + (size_t)row * 128 + col * 16);
        }
    }
    auto loadc = [&](int s, int c) {
        const int k0 = c * 64;
        {
            int row = t >> 3, col = t & 7;
            uint32_t off = SWZ128((uint32_t)(row * 128 + col * 16));
            CP16(smb + FB_ST(s) + off,
                 (const char*)(fh + (size_t)(b * NPIX + k0 + row) * KPAD) + col * 16);
        }
        #pragma unroll
        for (int i = 0; i < 4; i++) {
            int idx = t + 512 * i;
            int row = idx >> 3, col = idx & 7;
            uint32_t off = SWZ128((uint32_t)(row * 128 + col * 16));
            CP16(smb + FB_ST(s) + 8192 + off,
                 (const char*)(hmT + ((size_t)(b * CDIM + row) * NPIX + k0)) + col * 16);
        }
    };
    loadc(0, 0);
    CP_COMMIT();

    float acc[16][4];
    #pragma unroll
    for (int nt = 0; nt < 16; nt++)
        #pragma unroll
        for (int i = 0; i < 4; i++) acc[nt][i] = 0.f;
    float sum0 = 0.f, sum1 = 0.f;

    for (int c = 0; c < 64; c++) {
        CP_WAIT0();
        __syncthreads();

        const uint32_t gH = smb + FB_G_HI, gL = smb + FB_G_LO;
        const uint32_t stb = smb + FB_ST(c & 1);
        const uint32_t fH = stb, hmS = stb + 8192;
        const uint32_t pH = smb + FB_P(c & 1);

        // ---- s-phase: rows 16wm x keys [32wn, 32wn+32), 2-term fp16 ----
        {
            uint32_t ah[2][4], al[2][4];
            #pragma unroll
            for (int ks = 0; ks < 2; ks++) {
                uint32_t off = SWZ128((uint32_t)((16 * wm + (lane & 15)) * 128) + ks * 32 + kb);
                LDSM4(ah[ks], gH + off);
                LDSM4(al[ks], gL + off);
            }
            #pragma unroll
            for (int ntp = 0; ntp < 2; ntp++) {
                float fr[2][4] = {{0.f,0.f,0.f,0.f},{0.f,0.f,0.f,0.f}};
                #pragma unroll
                for (int ks = 0; ks < 2; ks++) {
                    uint32_t off = SWZ128((uint32_t)((32 * wn + ntp * 16 + (lane & 15)) * 128)
                                          + ks * 32 + kb);
                    uint32_t bh[4];
                    LDSM4(bh, fH + off);
                    #pragma unroll
                    for (int h = 0; h < 2; h++) {
                        uint32_t b0h = h ? bh[1] : bh[0], b1h = h ? bh[3] : bh[2];
                        MMAH16816(fr[h], ah[ks], b0h, b1h);
                        MMAH16816(fr[h], al[ks], b0h, b1h);
                    }
                }
                #pragma unroll
                for (int h = 0; h < 2; h++) {
                    int key = 32 * wn + ntp * 16 + h * 8 + 2 * q;
                    float p0 = ex2f(fmaf(fr[h][0], l2e, -mc0));
                    float p1 = ex2f(fmaf(fr[h][1], l2e, -mc0));
                    float p2 = ex2f(fmaf(fr[h][2], l2e, -mc1));
                    float p3 = ex2f(fmaf(fr[h][3], l2e, -mc1));
                    sum0 += p0 + p1;
                    sum1 += p2 + p3;
                    uint32_t a0 = SWZ128((uint32_t)((16 * wm + g) * 128 + key * 2));
                    uint32_t a1 = SWZ128((uint32_t)((16 * wm + 8 + g) * 128 + key * 2));
                    STS32(pH + a0, packh_hi(p0, p1));
                    STS32(pH + a1, packh_hi(p2, p3));
                }
            }
        }
        __syncthreads();

        if (c + 1 < 64) { loadc((c + 1) & 1, c + 1); CP_COMMIT(); }

        // ---- o-phase: rows 16wm x channels [128wn, 128wn+128), 1-term ----
        #pragma unroll
        for (int ks = 0; ks < 4; ks++) {
            uint32_t offA = SWZ128((uint32_t)((16 * wm + (lane & 15)) * 128) + ks * 32 + kb);
            uint32_t aph[4];
            LDSM4(aph, pH + offA);
            #pragma unroll
            for (int ntp = 0; ntp < 8; ntp++) {
                uint32_t off = SWZ128((uint32_t)((128 * wn + ntp * 16 + (lane & 15)) * 128)
                                      + ks * 32 + kb);
                uint32_t bh[4];
                LDSM4(bh, hmS + off);
                MMAH16816(acc[ntp * 2 + 0], aph, bh[0], bh[2]);
                MMAH16816(acc[ntp * 2 + 1], aph, bh[1], bh[3]);
            }
        }
    }

    // ---- normalize + store o split-bf16 ----
    sum0 += __shfl_xor_sync(~0u, sum0, 1);
    sum0 += __shfl_xor_sync(~0u, sum0, 2);
    sum1 += __shfl_xor_sync(~0u, sum1, 1);
    sum1 += __shfl_xor_sync(~0u, sum1, 2);
    if ((lane & 3) == 0) {
        rsum[wn][16 * wm + g] = sum0;
        rsum[wn][16 * wm + 8 + g] = sum1;
    }
    __syncthreads();
    const float inv0 = 1.f / (rsum[0][16 * wm + g]     + rsum[1][16 * wm + g]);
    const float inv1 = 1.f / (rsum[0][16 * wm + 8 + g] + rsum[1][16 * wm + 8 + g]);

    #pragma unroll
    for (int nt = 0; nt < 16; nt++) {
        int ch = 128 * wn + nt * 8 + 2 * q;
        float v0 = acc[nt][0] * inv0, v1 = acc[nt][1] * inv0;
        float v2 = acc[nt][2] * inv1, v3 = acc[nt][3] * inv1;
        size_t o0 = ((size_t)(b * NPIX + m0 + 16 * wm + g)) * CDIM + ch;
        size_t o1 = ((size_t)(b * NPIX + m0 + 16 * wm + 8 + g)) * CDIM + ch;
        *(uint32_t*)(oh + o0) = pack_hi(v0, v1);
        *(uint32_t*)(ol + o0) = pack_lo(v0, v1);
        *(uint32_t*)(oh + o1) = pack_hi(v2, v3);
        *(uint32_t*)(ol + o1) = pack_lo(v2, v3);
    }
}

// ---------------------------------------------------------------------------
extern "C" void kernel_launch(void* const* d_in, const int* in_sizes, int n_in,
                              void* d_out, int out_size)
{
    (void)in_sizes; (void)n_in; (void)out_size;
    const float* x  = (const float*)d_in[0];
    const float* Wf = (const float*)d_in[1];
    const float* bf = (const float*)d_in[2];
    const float* Wg = (const float*)d_in[3];
    const float* bg = (const float*)d_in[4];
    const float* Wh = (const float*)d_in[5];
    const float* bh = (const float*)d_in[6];
    const float* Wv = (const float*)d_in[7];
    const float* bv = (const float*)d_in[8];
    float* out = (float*)d_out;

    bf16 *xh, *xl, *fgth, *fgtl, *whth, *whtl, *wvth, *wvtl, *oh, *ol;
    __half *fh, *fl, *gh, *gl, *th;
    float* pm;
    cudaGetSymbolAddress((void**)&xh,   g_xh);
    cudaGetSymbolAddress((void**)&xl,   g_xl);
    cudaGetSymbolAddress((void**)&fgth, g_wfgt_h);
    cudaGetSymbolAddress((void**)&fgtl, g_wfgt_l);
    cudaGetSymbolAddress((void**)&whth, g_wht_h);
    cudaGetSymbolAddress((void**)&whtl, g_wht_l);
    cudaGetSymbolAddress((void**)&wvth, g_wvt_h);
    cudaGetSymbolAddress((void**)&wvtl, g_wvt_l);
    cudaGetSymbolAddress((void**)&fh,   g_fh);
    cudaGetSymbolAddress((void**)&fl,   g_fl);
    cudaGetSymbolAddress((void**)&gh,   g_gh);
    cudaGetSymbolAddress((void**)&gl,   g_gl);
    cudaGetSymbolAddress((void**)&th,   g_th);
    cudaGetSymbolAddress((void**)&pm,   g_m);
    cudaGetSymbolAddress((void**)&oh,   g_oh);
    cudaGetSymbolAddress((void**)&ol,   g_ol);

    const int SM64_128 = 2 * (2 * 64 * 128 + 2 * 128 * 128);  // 98304
    const int SM64_64  = 2 * (2 * 64 * 128 + 2 * 64 * 128);   // 65536
    cudaFuncSetAttribute(gemm_nt<64, 64, 1, 0, 0, 2>,
                         cudaFuncAttributeMaxDynamicSharedMemorySize, SM64_64);
    cudaFuncSetAttribute(gemm_nt<64, 128, 1, 2, 0, 1>,
                         cudaFuncAttributeMaxDynamicSharedMemorySize, SM64_128);
    cudaFuncSetAttribute(gemm_nt<64, 128, 0, 1, 1, 0>,
                         cudaFuncAttributeMaxDynamicSharedMemorySize, SM64_128);
    cudaFuncSetAttribute(rowmax_kernel,
                         cudaFuncAttributeMaxDynamicSharedMemorySize, RA_SMEM);
    cudaFuncSetAttribute(fused_attn_kernel,
                         cudaFuncAttributeMaxDynamicSharedMemorySize, FB_SMEM);

    xsplit_kernel<<<MROWS * CDIM / 4 / 256, 256>>>(x, xh, xl);
    wprep_kernel<<<576, 256>>>(Wf, Wg, Wh, Wv,
                               fgth, fgtl, whth, whtl, wvth, wvtl);

    // fg proj: f,g split fp16 (K padded to 64).  MT=64, NT=64, 128 thr
    gemm_nt<64, 64, 1, 0, 0, 2><<<dim3(MROWS / 64, 1, 1), 128, SM64_64>>>(
        xh, xl, 0, fgth, fgtl, 0,
        fh, fl, gh, gl, 0, KPAD, bf, bg, nullptr, CDIM);

    // hm^T proj: single fp16, bias on rows.  MT=64, NT=128
    gemm_nt<64, 128, 1, 2, 0, 1><<<dim3(CDIM / 64, MROWS / 128, 1), 128, SM64_128>>>(
        whth, whtl, 0, xh, xl, 0,
        th, nullptr, nullptr, nullptr, 0, 0, bh, nullptr, nullptr, CDIM);

    // pass A: approx row maxes of s (1-term fp16)
    rowmax_kernel<<<dim3(NPIX / 128, 1, BATCH), 256, RA_SMEM>>>(gh, fh, pm);

    // pass B: fused exp + o (unnormalized) + normalize -> o split bf16
    fused_attn_kernel<<<dim3(NPIX / 128, 1, BATCH), 512, FB_SMEM>>>(
        gh, gl, fh, th, pm, oh, ol);

    // out = x + o @ Wv + bv (fp32).  MT=64, NT=128
    gemm_nt<64, 128, 0, 1, 1, 0><<<dim3(MROWS / 64, CDIM / 128, 1), 128, SM64_128>>>(
        oh, ol, 0, wvth, wvtl, 0,
        out, nullptr, nullptr, nullptr, 0, CDIM, bv, nullptr, x, CDIM);
}

// round 17
// speedup vs baseline: 5.1719x; 1.1289x over previous
#include <cuda_runtime.h>
#include <cuda_bf16.h>
#include <cuda_fp16.h>
#include <cstdint>

// ---------------------------------------------------------------------------
// SelfAttention (SAGAN-style), B=4, N=4096, C=256, Ck=32.
// Projections / v-proj: bf16 split 3-term mma.sync, MT=64 tiles.
// Attention core fp16:
//   pass A (rowmax): 1-term fp16, 256-key chunks
//   pass B (fused): register-resident p — each warp owns 16 rows x all keys x
//     all 256 channels; s C-fragment is repacked in registers directly into
//     the o-MMA A-fragment (identical lane layout). No p smem, 1 barrier/chunk.
// ---------------------------------------------------------------------------

#define BATCH 4
#define NPIX  4096
#define CDIM  256
#define CKDIM 32
#define MROWS 16384
#define KPAD  64

typedef __nv_bfloat16 bf16;

static __device__ __align__(16) bf16   g_xh[MROWS * CDIM];
static __device__ __align__(16) bf16   g_xl[MROWS * CDIM];
static __device__ __align__(16) bf16   g_wfgt_h[64 * CDIM];
static __device__ __align__(16) bf16   g_wfgt_l[64 * CDIM];
static __device__ __align__(16) bf16   g_wht_h[CDIM * CDIM];
static __device__ __align__(16) bf16   g_wht_l[CDIM * CDIM];
static __device__ __align__(16) bf16   g_wvt_h[CDIM * CDIM];
static __device__ __align__(16) bf16   g_wvt_l[CDIM * CDIM];
static __device__ __align__(16) __half g_fh[MROWS * KPAD];
static __device__ __align__(16) __half g_fl[MROWS * KPAD];   // written, unused
static __device__ __align__(16) __half g_gh[MROWS * KPAD];
static __device__ __align__(16) __half g_gl[MROWS * KPAD];
static __device__ __align__(16) __half g_th[(size_t)BATCH * CDIM * NPIX];
static __device__ __align__(16) float  g_m[MROWS];
static __device__ __align__(16) bf16   g_oh[MROWS * CDIM];
static __device__ __align__(16) bf16   g_ol[MROWS * CDIM];

// --- PTX helpers ------------------------------------------------------------
__device__ __forceinline__ uint32_t smem_u32(const void* p) {
    uint32_t a;
    asm("{ .reg .u64 t; cvta.to.shared.u64 t, %1; cvt.u32.u64 %0, t; }"
        : "=r"(a) : "l"(p));
    return a;
}

#define SWZ128(off) ((off) ^ (((off) >> 3) & 0x70u))

#define LDSM4(r, addr) \
    asm volatile("ldmatrix.sync.aligned.m8n8.x4.shared.b16 {%0,%1,%2,%3}, [%4];" \
        : "=r"((r)[0]), "=r"((r)[1]), "=r"((r)[2]), "=r"((r)[3]) : "r"(addr))

#define MMA16816(d, a, b0, b1) \
    asm volatile("mma.sync.aligned.m16n8k16.row.col.f32.bf16.bf16.f32 " \
        "{%0,%1,%2,%3}, {%4,%5,%6,%7}, {%8,%9}, {%0,%1,%2,%3};" \
        : "+f"((d)[0]), "+f"((d)[1]), "+f"((d)[2]), "+f"((d)[3]) \
        : "r"((a)[0]), "r"((a)[1]), "r"((a)[2]), "r"((a)[3]), "r"(b0), "r"(b1))

#define MMAH16816(d, a, b0, b1) \
    asm volatile("mma.sync.aligned.m16n8k16.row.col.f32.f16.f16.f32 " \
        "{%0,%1,%2,%3}, {%4,%5,%6,%7}, {%8,%9}, {%0,%1,%2,%3};" \
        : "+f"((d)[0]), "+f"((d)[1]), "+f"((d)[2]), "+f"((d)[3]) \
        : "r"((a)[0]), "r"((a)[1]), "r"((a)[2]), "r"((a)[3]), "r"(b0), "r"(b1))

#define CP16(smaddr, gptr) \
    asm volatile("cp.async.cg.shared.global [%0], [%1], 16;" \
        :: "r"(smaddr), "l"(gptr))
#define CP_COMMIT() asm volatile("cp.async.commit_group;" ::: "memory")
#define CP_WAIT1()  asm volatile("cp.async.wait_group 1;" ::: "memory")
#define CP_WAIT0()  asm volatile("cp.async.wait_group 0;" ::: "memory")

__device__ __forceinline__ float ex2f(float x) {
    float r; asm("ex2.approx.f32 %0, %1;" : "=f"(r) : "f"(x)); return r;
}
__device__ __forceinline__ uint32_t pack_hi(float a, float b) {
    __nv_bfloat162 h; h.x = __float2bfloat16(a); h.y = __float2bfloat16(b);
    return *(uint32_t*)&h;
}
__device__ __forceinline__ uint32_t pack_lo(float a, float b) {
    bf16 ha = __float2bfloat16(a), hb = __float2bfloat16(b);
    __nv_bfloat162 l;
    l.x = __float2bfloat16(a - __bfloat162float(ha));
    l.y = __float2bfloat16(b - __bfloat162float(hb));
    return *(uint32_t*)&l;
}
__device__ __forceinline__ uint32_t packh_hi(float a, float b) {
    __half2 h = __floats2half2_rn(a, b);
    return *(uint32_t*)&h;
}
__device__ __forceinline__ uint32_t packh_lo(float a, float b) {
    float ra = __half2float(__float2half_rn(a));
    float rb = __half2float(__float2half_rn(b));
    __half2 l = __floats2half2_rn(a - ra, b - rb);
    return *(uint32_t*)&l;
}

// ---------------------------------------------------------------------------
__global__ __launch_bounds__(256)
void xsplit_kernel(const float* __restrict__ X,
                   bf16* __restrict__ H, bf16* __restrict__ L)
{
    int i = blockIdx.x * 256 + threadIdx.x;
    float4 v = reinterpret_cast<const float4*>(X)[i];
    reinterpret_cast<uint32_t*>(H + (size_t)i * 4)[0] = pack_hi(v.x, v.y);
    reinterpret_cast<uint32_t*>(H + (size_t)i * 4)[1] = pack_hi(v.z, v.w);
    reinterpret_cast<uint32_t*>(L + (size_t)i * 4)[0] = pack_lo(v.x, v.y);
    reinterpret_cast<uint32_t*>(L + (size_t)i * 4)[1] = pack_lo(v.z, v.w);
}

// ---------------------------------------------------------------------------
__global__ __launch_bounds__(256)
void wprep_kernel(const float* __restrict__ Wf, const float* __restrict__ Wg,
                  const float* __restrict__ Wh, const float* __restrict__ Wv,
                  bf16* __restrict__ FGh, bf16* __restrict__ FGl,
                  bf16* __restrict__ WHh, bf16* __restrict__ WHl,
                  bf16* __restrict__ WVh, bf16* __restrict__ WVl)
{
    int r = blockIdx.x;
    int k = threadIdx.x;
    float w;
    bf16 *ph, *pl;
    int out;
    if (r < 64) {
        w = (r < 32) ? Wf[k * CKDIM + r] : Wg[k * CKDIM + (r - 32)];
        ph = FGh; pl = FGl; out = r * CDIM + k;
    } else if (r < 320) {
        int c = r - 64;
        w = Wh[k * CDIM + c];
        ph = WHh; pl = WHl; out = c * CDIM + k;
    } else {
        int c = r - 320;
        w = Wv[k * CDIM + c];
        ph = WVh; pl = WVl; out = c * CDIM + k;
    }
    bf16 h = __float2bfloat16(w);
    ph[out] = h;
    pl[out] = __float2bfloat16(w - __bfloat162float(h));
}

// ---------------------------------------------------------------------------
// Generic NT GEMM, bf16 split 3-term (proven).  MT in {64,128}, threads = 2*MT.
// ---------------------------------------------------------------------------
template<int MT, int NT, int OUT, int BIAS, int RES, int NMAP>
__global__ void __launch_bounds__(MT * 2, (MT == 64) ? 2 : 1)
gemm_nt(const bf16* __restrict__ Ah, const bf16* __restrict__ Al, long long sA,
        const bf16* __restrict__ Bh, const bf16* __restrict__ Bl, long long sB,
        void* __restrict__ C0, void* __restrict__ C1,
        void* __restrict__ C2, void* __restrict__ C3,
        long long sC, int ldC,
        const float* __restrict__ bias, const float* __restrict__ bias2,
        const float* __restrict__ resid, int K)
{
    extern __shared__ __align__(1024) char gsm[];
    constexpr int THREADS = MT * 2;
    constexpr int AHo = 0;
    constexpr int ALo = MT * 128;
    constexpr int BHo = 2 * MT * 128;
    constexpr int BLo = BHo + NT * 128;
    constexpr int STG = BHo + 2 * NT * 128;
    constexpr int BI  = (NT * 8) / THREADS;

    const int t    = threadIdx.x;
    const int lane = t & 31;
    const int wid  = t >> 5;
    const int wm   = wid >> 1;
    const int wn   = wid & 1;
    const int m0   = blockIdx.x * MT;
    const int n0   = blockIdx.y * NT;
    const int z    = blockIdx.z;

    const uint32_t smb = smem_u32(gsm);
    const bf16* pAh = Ah + (size_t)z * sA + (size_t)m0 * K;
    const bf16* pAl = Al + (size_t)z * sA + (size_t)m0 * K;
    const bf16* pBh = Bh + (size_t)z * sB + (size_t)n0 * K;
    const bf16* pBl = Bl + (size_t)z * sB + (size_t)n0 * K;

    float acc[2][NT / 16][4];
    #pragma unroll
    for (int mt = 0; mt < 2; mt++)
      #pragma unroll
      for (int nt = 0; nt < NT / 16; nt++)
        #pragma unroll
        for (int q = 0; q < 4; q++)
            acc[mt][nt][q] = 0.f;

    auto load_stage = [&](int s, int c) {
        const uint32_t sb = smb + s * STG;
        const int k0 = c * 64;
        #pragma unroll
        for (int i = 0; i < 4; i++) {
            int idx = t + THREADS * i;
            int row = idx >> 3, col = idx & 7;
            uint32_t off = SWZ128((uint32_t)(row * 128 + col * 16));
            CP16(sb + AHo + off, (const char*)(pAh + (size_t)row * K + k0) + col * 16);
            CP16(sb + ALo + off, (const char*)(pAl + (size_t)row * K + k0) + col * 16);
        }
        #pragma unroll
        for (int i = 0; i < BI; i++) {
            int idx = t + THREADS * i;
            int row = idx >> 3, col = idx & 7;
            uint32_t off = SWZ128((uint32_t)(row * 128 + col * 16));
            CP16(sb + BHo + off, (const char*)(pBh + (size_t)row * K + k0) + col * 16);
            CP16(sb + BLo + off, (const char*)(pBl + (size_t)row * K + k0) + col * 16);
        }
    };

    const int chunks = K >> 6;
    load_stage(0, 0);
    CP_COMMIT();

    for (int c = 0; c < chunks; ++c) {
        if (c + 1 < chunks) {
            load_stage((c + 1) & 1, c + 1);
            CP_COMMIT();
            CP_WAIT1();
        } else {
            CP_WAIT0();
        }
        __syncthreads();

        const uint32_t sb  = smb + (c & 1) * STG;
        const uint32_t sAh = sb + AHo, sAl = sb + ALo;
        const uint32_t sBh = sb + BHo, sBl = sb + BLo;

        #pragma unroll
        for (int ks = 0; ks < 4; ks++) {
            const uint32_t kbyte = ks * 32 + ((lane >> 4) << 4);

            uint32_t afh[2][4], afl[2][4];
            #pragma unroll
            for (int mt = 0; mt < 2; mt++) {
                int row = wm * 32 + mt * 16 + (lane & 15);
                uint32_t off = SWZ128((uint32_t)(row * 128) + kbyte);
                LDSM4(afh[mt], sAh + off);
                LDSM4(afl[mt], sAl + off);
            }

            #pragma unroll
            for (int ntp = 0; ntp < NT / 32; ntp++) {
                int row = wn * (NT / 2) + ntp * 16 + (lane & 15);
                uint32_t off = SWZ128((uint32_t)(row * 128) + kbyte);
                uint32_t bfh[4], bfl[4];
                LDSM4(bfh, sBh + off);
                LDSM4(bfl, sBl + off);
                #pragma unroll
                for (int h = 0; h < 2; h++) {
                    uint32_t b0h = h ? bfh[1] : bfh[0];
                    uint32_t b1h = h ? bfh[3] : bfh[2];
                    uint32_t b0l = h ? bfl[1] : bfl[0];
                    uint32_t b1l = h ? bfl[3] : bfl[2];
                    const int nt = ntp * 2 + h;
                    #pragma unroll
                    for (int mt = 0; mt < 2; mt++) {
                        MMA16816(acc[mt][nt], afh[mt], b0h, b1h);
                        MMA16816(acc[mt][nt], afh[mt], b0l, b1l);
                        MMA16816(acc[mt][nt], afl[mt], b0h, b1h);
                    }
                }
            }
        }
        __syncthreads();
    }

    const int g = lane >> 2;
    const int q = lane & 3;

    auto store2 = [&](int rg, int cg, float v0, float v1) {
        if constexpr (BIAS == 1) { v0 += bias[cg]; v1 += bias[cg + 1]; }
        if constexpr (BIAS == 2) { float bb = bias[rg]; v0 += bb; v1 += bb; }

        if constexpr (NMAP == 2) {
            bool isf = (cg < 32);
            float b0 = isf ? bias[cg]  : bias2[cg - 32];
            float b1 = isf ? bias[cg + 1] : bias2[cg - 31];
            v0 += b0; v1 += b1;
            uint32_t hp = packh_hi(v0, v1);
            uint32_t lp = packh_lo(v0, v1);
            size_t rowb = (size_t)rg * KPAD;
            if (isf) {
                *(uint32_t*)((__half*)C0 + rowb + cg) = hp;
                *(uint32_t*)((__half*)C1 + rowb + cg) = lp;
                *(uint32_t*)((__half*)C0 + rowb + cg + 32) = 0u;
                *(uint32_t*)((__half*)C1 + rowb + cg + 32) = 0u;
            } else {
                *(uint32_t*)((__half*)C2 + rowb + cg - 32) = hp;
                *(uint32_t*)((__half*)C3 + rowb + cg - 32) = lp;
                *(uint32_t*)((__half*)C2 + rowb + cg) = 0u;
                *(uint32_t*)((__half*)C3 + rowb + cg) = 0u;
            }
        } else if constexpr (NMAP == 1) {
            int bb = cg >> 12, nn = cg & 4095;
            size_t off = ((size_t)(bb * CDIM + rg)) * NPIX + nn;
            *(uint32_t*)((__half*)C0 + off) = packh_hi(v0, v1);
        } else if constexpr (OUT == 0) {
            size_t off = (size_t)z * sC + (size_t)rg * ldC + cg;
            if constexpr (RES) {
                v0 += resid[(size_t)rg * ldC + cg];
                v1 += resid[(size_t)rg * ldC + cg + 1];
            }
            *(float2*)((float*)C0 + off) = make_float2(v0, v1);
        } else {
            size_t off = (size_t)z * sC + (size_t)rg * ldC + cg;
            *(uint32_t*)((bf16*)C0 + off) = pack_hi(v0, v1);
            *(uint32_t*)((bf16*)C1 + off) = pack_lo(v0, v1);
        }
    };

    #pragma unroll
    for (int mt = 0; mt < 2; mt++) {
        #pragma unroll
        for (int nt = 0; nt < NT / 16; nt++) {
            int rg = m0 + wm * 32 + mt * 16 + g;
            int cg = n0 + wn * (NT / 2) + nt * 8 + q * 2;
            store2(rg,     cg, acc[mt][nt][0], acc[mt][nt][1]);
            store2(rg + 8, cg, acc[mt][nt][2], acc[mt][nt][3]);
        }
    }
}

// ---------------------------------------------------------------------------
// Pass A: per-row approx max of s, 1-term fp16, 256-key chunks.
// ---------------------------------------------------------------------------
#define RA_G 0
#define RA_ST(s) (16384 + (s) * 32768)
#define RA_SMEM  81920

__global__ void __launch_bounds__(256, 1)
rowmax_kernel(const __half* __restrict__ gh, const __half* __restrict__ fh,
              float* __restrict__ M)
{
    extern __shared__ __align__(1024) char rsm[];
    const int t = threadIdx.x, lane = t & 31, w = t >> 5;
    const int b = blockIdx.z, m0 = blockIdx.x * 128;
    const uint32_t smb = smem_u32(rsm);
    const uint32_t kb = (uint32_t)((lane >> 4) << 4);

    {
        const char* sH = (const char*)(gh + (size_t)(b * NPIX + m0) * KPAD);
        #pragma unroll
        for (int i = 0; i < 4; i++) {
            int idx = t + 256 * i;
            int row = idx >> 3, col = idx & 7;
            uint32_t off = SWZ128((uint32_t)(row * 128 + col * 16));
            CP16(smb + RA_G + off, sH + (size_t)row * 128 + col * 16);
        }
    }
    auto loadf = [&](int s, int c) {
        const int k0 = c * 256;
        const char* sH = (const char*)(fh + (size_t)(b * NPIX + k0) * KPAD);
        #pragma unroll
        for (int i = 0; i < 8; i++) {
            int idx = t + 256 * i;
            int row = idx >> 3, col = idx & 7;
            uint32_t off = SWZ128((uint32_t)(row * 128 + col * 16));
            CP16(smb + RA_ST(s) + off, sH + (size_t)row * 128 + col * 16);
        }
    };
    loadf(0, 0);
    CP_COMMIT();

    float mx0 = -3.4e38f, mx1 = -3.4e38f;

    for (int c = 0; c < 16; c++) {
        if (c + 1 < 16) { loadf((c + 1) & 1, c + 1); CP_COMMIT(); CP_WAIT1(); }
        else            { CP_WAIT0(); }
        __syncthreads();

        const uint32_t gH = smb + RA_G;
        const uint32_t fH = smb + RA_ST(c & 1);

        uint32_t ah[2][4];
        #pragma unroll
        for (int ks = 0; ks < 2; ks++) {
            uint32_t off = SWZ128((uint32_t)((16 * w + (lane & 15)) * 128) + ks * 32 + kb);
            LDSM4(ah[ks], gH + off);
        }
        #pragma unroll
        for (int ntp = 0; ntp < 16; ntp++) {
            float fr[2][4] = {{0.f,0.f,0.f,0.f},{0.f,0.f,0.f,0.f}};
            #pragma unroll
            for (int ks = 0; ks < 2; ks++) {
                uint32_t off = SWZ128((uint32_t)((ntp * 16 + (lane & 15)) * 128) + ks * 32 + kb);
                uint32_t bh[4];
                LDSM4(bh, fH + off);
                MMAH16816(fr[0], ah[ks], bh[0], bh[2]);
                MMAH16816(fr[1], ah[ks], bh[1], bh[3]);
            }
            #pragma unroll
            for (int h = 0; h < 2; h++) {
                mx0 = fmaxf(mx0, fmaxf(fr[h][0], fr[h][1]));
                mx1 = fmaxf(mx1, fmaxf(fr[h][2], fr[h][3]));
            }
        }
        __syncthreads();
    }

    mx0 = fmaxf(mx0, __shfl_xor_sync(~0u, mx0, 1));
    mx0 = fmaxf(mx0, __shfl_xor_sync(~0u, mx0, 2));
    mx1 = fmaxf(mx1, __shfl_xor_sync(~0u, mx1, 1));
    mx1 = fmaxf(mx1, __shfl_xor_sync(~0u, mx1, 2));
    if ((lane & 3) == 0) {
        int r = m0 + 16 * w + (lane >> 2);
        M[(size_t)b * NPIX + r]     = mx0;
        M[(size_t)b * NPIX + r + 8] = mx1;
    }
}

// ---------------------------------------------------------------------------
// Pass B: fused s -> exp -> o -> normalize.  fp16 core, register-resident p.
// 256 threads, 8 warps; warp w owns rows [16w,16w+16) x all keys x all 256 ch.
// acc = 32 n8-tiles x 4 = 128 fp32 regs/thread.  One __syncthreads per chunk.
// ---------------------------------------------------------------------------
#define FB_G_HI 0
#define FB_G_LO 16384
#define FB_ST(s) (32768 + (s) * 40960)   // f_hi 8K, hm 32K
#define FB_SMEM  114688

__global__ void __launch_bounds__(256, 1)
fused_attn_kernel(const __half* __restrict__ gh, const __half* __restrict__ gl,
                  const __half* __restrict__ fh,
                  const __half* __restrict__ hmT,
                  const float* __restrict__ M,
                  bf16* __restrict__ oh, bf16* __restrict__ ol)
{
    extern __shared__ __align__(1024) char fsm[];
    const int t = threadIdx.x, lane = t & 31, w = t >> 5;   // w = 0..7
    const int b = blockIdx.z, m0 = blockIdx.x * 128;
    const int g = lane >> 2, q = lane & 3;
    const uint32_t smb = smem_u32(fsm);
    const uint32_t kb = (uint32_t)((lane >> 4) << 4);
    const float l2e = 1.4426950408889634f;

    const float mc0 = M[(size_t)b * NPIX + m0 + 16 * w + g] * l2e;
    const float mc1 = M[(size_t)b * NPIX + m0 + 16 * w + 8 + g] * l2e;

    // g tiles: 128 rows x 128B, hi + lo (4 CP16/thread per array)
    {
        const char* sH = (const char*)(gh + (size_t)(b * NPIX + m0) * KPAD);
        const char* sL = (const char*)(gl + (size_t)(b * NPIX + m0) * KPAD);
        #pragma unroll
        for (int i = 0; i < 4; i++) {
            int idx = t + 256 * i;
            int row = idx >> 3, col = idx & 7;
            uint32_t off = SWZ128((uint32_t)(row * 128 + col * 16));
            CP16(smb + FB_G_HI + off, sH + (size_t)row * 128 + col * 16);
            CP16(smb + FB_G_LO + off, sL + (size_t)row * 128 + col * 16);
        }
    }
    auto loadc = [&](int s, int c) {
        const int k0 = c * 64;
        #pragma unroll
        for (int i = 0; i < 2; i++) {      // f: 64 rows x 8 units
            int idx = t + 256 * i;
            int row = idx >> 3, col = idx & 7;
            uint32_t off = SWZ128((uint32_t)(row * 128 + col * 16));
            CP16(smb + FB_ST(s) + off,
                 (const char*)(fh + (size_t)(b * NPIX + k0 + row) * KPAD) + col * 16);
        }
        #pragma unroll
        for (int i = 0; i < 8; i++) {      // hm: 256 rows x 8 units
            int idx = t + 256 * i;
            int row = idx >> 3, col = idx & 7;
            uint32_t off = SWZ128((uint32_t)(row * 128 + col * 16));
            CP16(smb + FB_ST(s) + 8192 + off,
                 (const char*)(hmT + ((size_t)(b * CDIM + row) * NPIX + k0)) + col * 16);
        }
    };
    loadc(0, 0);
    CP_COMMIT();

    float acc[32][4];
    #pragma unroll
    for (int nt = 0; nt < 32; nt++)
        #pragma unroll
        for (int i = 0; i < 4; i++) acc[nt][i] = 0.f;
    float sum0 = 0.f, sum1 = 0.f;

    const uint32_t gH = smb + FB_G_HI, gL = smb + FB_G_LO;

    for (int c = 0; c < 64; c++) {
        CP_WAIT0();
        __syncthreads();
        if (c + 1 < 64) { loadc((c + 1) & 1, c + 1); CP_COMMIT(); }

        const uint32_t stb = smb + FB_ST(c & 1);
        const uint32_t fH = stb, hmS = stb + 8192;

        // a-frags for s (own rows, k 0..31 real)
        uint32_t ah[2][4], al[2][4];
        #pragma unroll
        for (int ks = 0; ks < 2; ks++) {
            uint32_t off = SWZ128((uint32_t)((16 * w + (lane & 15)) * 128) + ks * 32 + kb);
            LDSM4(ah[ks], gH + off);
            LDSM4(al[ks], gL + off);
        }

        #pragma unroll
        for (int ntp = 0; ntp < 4; ntp++) {      // key-16-tiles
            // ---- s: 2-term fp16 ----
            float fr[2][4] = {{0.f,0.f,0.f,0.f},{0.f,0.f,0.f,0.f}};
            #pragma unroll
            for (int ks = 0; ks < 2; ks++) {
                uint32_t off = SWZ128((uint32_t)((ntp * 16 + (lane & 15)) * 128)
                                      + ks * 32 + kb);
                uint32_t bh[4];
                LDSM4(bh, fH + off);
                #pragma unroll
                for (int h = 0; h < 2; h++) {
                    MMAH16816(fr[h], ah[ks], bh[h], bh[h + 2]);
                    MMAH16816(fr[h], al[ks], bh[h], bh[h + 2]);
                }
            }
            // ---- exp + repack C-frag -> o A-frag (registers only) ----
            float p00 = ex2f(fmaf(fr[0][0], l2e, -mc0));
            float p01 = ex2f(fmaf(fr[0][1], l2e, -mc0));
            float p02 = ex2f(fmaf(fr[0][2], l2e, -mc1));
            float p03 = ex2f(fmaf(fr[0][3], l2e, -mc1));
            float p10 = ex2f(fmaf(fr[1][0], l2e, -mc0));
            float p11 = ex2f(fmaf(fr[1][1], l2e, -mc0));
            float p12 = ex2f(fmaf(fr[1][2], l2e, -mc1));
            float p13 = ex2f(fmaf(fr[1][3], l2e, -mc1));
            sum0 += p00 + p01 + p10 + p11;
            sum1 += p02 + p03 + p12 + p13;
            uint32_t ap[4];
            ap[0] = packh_hi(p00, p01);   // A[g][2q..],    k 0..7 of tile
            ap[1] = packh_hi(p02, p03);   // A[g+8][2q..],  k 0..7
            ap[2] = packh_hi(p10, p11);   // A[g][2q..],    k 8..15
            ap[3] = packh_hi(p12, p13);   // A[g+8][2q..],  k 8..15

            // ---- o: 1-term, all 256 channels for this key-16-slice ----
            #pragma unroll
            for (int ctp = 0; ctp < 16; ctp++) {
                uint32_t off = SWZ128((uint32_t)((ctp * 16 + (lane & 15)) * 128)
                                      + ntp * 32 + kb);
                uint32_t bh2[4];
                LDSM4(bh2, hmS + off);
                MMAH16816(acc[ctp * 2 + 0], ap, bh2[0], bh2[2]);
                MMAH16816(acc[ctp * 2 + 1], ap, bh2[1], bh2[3]);
            }
        }
    }

    // ---- normalize (warp-private rows) + store o split-bf16 ----
    sum0 += __shfl_xor_sync(~0u, sum0, 1);
    sum0 += __shfl_xor_sync(~0u, sum0, 2);
    sum1 += __shfl_xor_sync(~0u, sum1, 1);
    sum1 += __shfl_xor_sync(~0u, sum1, 2);
    const float inv0 = 1.f / sum0;
    const float inv1 = 1.f / sum1;

    #pragma unroll
    for (int nt = 0; nt < 32; nt++) {
        int ch = nt * 8 + 2 * q;
        float v0 = acc[nt][0] * inv0, v1 = acc[nt][1] * inv0;
        float v2 = acc[nt][2] * inv1, v3 = acc[nt][3] * inv1;
        size_t o0 = ((size_t)(b * NPIX + m0 + 16 * w + g)) * CDIM + ch;
        size_t o1 = ((size_t)(b * NPIX + m0 + 16 * w + 8 + g)) * CDIM + ch;
        *(uint32_t*)(oh + o0) = pack_hi(v0, v1);
        *(uint32_t*)(ol + o0) = pack_lo(v0, v1);
        *(uint32_t*)(oh + o1) = pack_hi(v2, v3);
        *(uint32_t*)(ol + o1) = pack_lo(v2, v3);
    }
}

// ---------------------------------------------------------------------------
extern "C" void kernel_launch(void* const* d_in, const int* in_sizes, int n_in,
                              void* d_out, int out_size)
{
    (void)in_sizes; (void)n_in; (void)out_size;
    const float* x  = (const float*)d_in[0];
    const float* Wf = (const float*)d_in[1];
    const float* bf = (const float*)d_in[2];
    const float* Wg = (const float*)d_in[3];
    const float* bg = (const float*)d_in[4];
    const float* Wh = (const float*)d_in[5];
    const float* bh = (const float*)d_in[6];
    const float* Wv = (const float*)d_in[7];
    const float* bv = (const float*)d_in[8];
    float* out = (float*)d_out;

    bf16 *xh, *xl, *fgth, *fgtl, *whth, *whtl, *wvth, *wvtl, *oh, *ol;
    __half *fh, *fl, *gh, *gl, *th;
    float* pm;
    cudaGetSymbolAddress((void**)&xh,   g_xh);
    cudaGetSymbolAddress((void**)&xl,   g_xl);
    cudaGetSymbolAddress((void**)&fgth, g_wfgt_h);
    cudaGetSymbolAddress((void**)&fgtl, g_wfgt_l);
    cudaGetSymbolAddress((void**)&whth, g_wht_h);
    cudaGetSymbolAddress((void**)&whtl, g_wht_l);
    cudaGetSymbolAddress((void**)&wvth, g_wvt_h);
    cudaGetSymbolAddress((void**)&wvtl, g_wvt_l);
    cudaGetSymbolAddress((void**)&fh,   g_fh);
    cudaGetSymbolAddress((void**)&fl,   g_fl);
    cudaGetSymbolAddress((void**)&gh,   g_gh);
    cudaGetSymbolAddress((void**)&gl,   g_gl);
    cudaGetSymbolAddress((void**)&th,   g_th);
    cudaGetSymbolAddress((void**)&pm,   g_m);
    cudaGetSymbolAddress((void**)&oh,   g_oh);
    cudaGetSymbolAddress((void**)&ol,   g_ol);

    const int SM64_128 = 2 * (2 * 64 * 128 + 2 * 128 * 128);  // 98304
    const int SM64_64  = 2 * (2 * 64 * 128 + 2 * 64 * 128);   // 65536
    cudaFuncSetAttribute(gemm_nt<64, 64, 1, 0, 0, 2>,
                         cudaFuncAttributeMaxDynamicSharedMemorySize, SM64_64);
    cudaFuncSetAttribute(gemm_nt<64, 128, 1, 2, 0, 1>,
                         cudaFuncAttributeMaxDynamicSharedMemorySize, SM64_128);
    cudaFuncSetAttribute(gemm_nt<64, 128, 0, 1, 1, 0>,
                         cudaFuncAttributeMaxDynamicSharedMemorySize, SM64_128);
    cudaFuncSetAttribute(rowmax_kernel,
                         cudaFuncAttributeMaxDynamicSharedMemorySize, RA_SMEM);
    cudaFuncSetAttribute(fused_attn_kernel,
                         cudaFuncAttributeMaxDynamicSharedMemorySize, FB_SMEM);

    xsplit_kernel<<<MROWS * CDIM / 4 / 256, 256>>>(x, xh, xl);
    wprep_kernel<<<576, 256>>>(Wf, Wg, Wh, Wv,
                               fgth, fgtl, whth, whtl, wvth, wvtl);

    // fg proj: f,g split fp16 (K padded to 64)
    gemm_nt<64, 64, 1, 0, 0, 2><<<dim3(MROWS / 64, 1, 1), 128, SM64_64>>>(
        xh, xl, 0, fgth, fgtl, 0,
        fh, fl, gh, gl, 0, KPAD, bf, bg, nullptr, CDIM);

    // hm^T proj: single fp16, bias on rows
    gemm_nt<64, 128, 1, 2, 0, 1><<<dim3(CDIM / 64, MROWS / 128, 1), 128, SM64_128>>>(
        whth, whtl, 0, xh, xl, 0,
        th, nullptr, nullptr, nullptr, 0, 0, bh, nullptr, nullptr, CDIM);

    // pass A: approx row maxes of s (1-term fp16, 256-key chunks)
    rowmax_kernel<<<dim3(NPIX / 128, 1, BATCH), 256, RA_SMEM>>>(gh, fh, pm);

    // pass B: fused exp + o (register-resident p) -> o split bf16
    fused_attn_kernel<<<dim3(NPIX / 128, 1, BATCH), 256, FB_SMEM>>>(
        gh, gl, fh, th, pm, oh, ol);

    // out = x + o @ Wv + bv (fp32)
    gemm_nt<64, 128, 0, 1, 1, 0><<<dim3(MROWS / 64, CDIM / 128, 1), 128, SM64_128>>>(
        oh, ol, 0, wvth, wvtl, 0,
        out, nullptr, nullptr, nullptr, 0, CDIM, bv, nullptr, x, CDIM);
}